// round 13
// baseline (speedup 1.0000x reference)
#include <cuda_runtime.h>
#include <cuda_bf16.h>
#include <math.h>
#include <cstdint>

#define BDIM 32
#define TDIM 32
#define LDIM 128
#define LOG_L 7

// ================= scratch (static device globals) =================
__device__ float g_xg1[(size_t)TDIM*BDIM*LDIM*256];   // [T][B][L][4F1] (gate-interleaved)
__device__ float g_xg2[(size_t)TDIM*BDIM*LDIM*512];   // [T][B][L][4F2]
__device__ float g_xg3[(size_t)TDIM*BDIM*LDIM*1024];  // [T][B][L][4F3]
__device__ float g_h1 [(size_t)TDIM*BDIM*LDIM*64];    // [T][B][L][F1]
__device__ float g_h2 [(size_t)TDIM*BDIM*LDIM*128];   // [T][B][L][F2]
__device__ float g_hst[(size_t)BDIM*LDIM*256];
__device__ float g_cst[(size_t)BDIM*LDIM*256];
__device__ float g_prt[(size_t)8*BDIM*1024];
__device__ float g_a1 [(size_t)BDIM*1024];
__device__ float g_a2 [(size_t)BDIM*512];
__device__ float g_pb1[256], g_pb2[512], g_pb3[1024];
__device__ float g_wx1p[3*256];

// bf16 hi/lo activations
__device__ __nv_bfloat16 g_hhi[(size_t)BDIM*LDIM*256];
__device__ __nv_bfloat16 g_hlo[(size_t)BDIM*LDIM*256];
__device__ __nv_bfloat16 g_bn1h[(size_t)TDIM*BDIM*LDIM*64];
__device__ __nv_bfloat16 g_bn1l[(size_t)TDIM*BDIM*LDIM*64];
__device__ __nv_bfloat16 g_bn2h[(size_t)TDIM*BDIM*LDIM*128];
__device__ __nv_bfloat16 g_bn2l[(size_t)TDIM*BDIM*LDIM*128];

// bf16 hi/lo weights, [N,K] layout, N gate-interleaved (n' = 4f+g)
__device__ __nv_bfloat16 g_wh1h[256*192],  g_wh1l[256*192];
__device__ __nv_bfloat16 g_wx2h[512*192],  g_wx2l[512*192];
__device__ __nv_bfloat16 g_wh2h[512*384],  g_wh2l[512*384];
__device__ __nv_bfloat16 g_wx3h[1024*384], g_wx3l[1024*384];
__device__ __nv_bfloat16 g_wh3h[1024*768], g_wh3l[1024*768];

// ================= helpers =================
__device__ __forceinline__ uint32_t smem_to_u32(const void* p) {
    uint32_t a;
    asm("{ .reg .u64 t; cvta.to.shared.u64 t, %1; cvt.u32.u64 %0, t; }" : "=r"(a) : "l"(p));
    return a;
}
__device__ __forceinline__ void cp_async16(uint32_t saddr, const void* gaddr, uint32_t sz) {
    asm volatile("cp.async.cg.shared.global [%0], [%1], 16, %2;"
                 :: "r"(saddr), "l"(gaddr), "r"(sz));
}
#define CP_COMMIT() asm volatile("cp.async.commit_group;" ::: "memory")
#define CP_WAIT(n)  asm volatile("cp.async.wait_group %0;" :: "n"(n) : "memory")
#define LDSM_X4(r, addr) \
    asm volatile("ldmatrix.sync.aligned.m8n8.x4.shared.b16 {%0,%1,%2,%3}, [%4];" \
        : "=r"((r)[0]), "=r"((r)[1]), "=r"((r)[2]), "=r"((r)[3]) : "r"(addr))

__device__ __forceinline__ void mma16816(float* c, const uint32_t* a,
                                         uint32_t b0, uint32_t b1) {
    asm volatile("mma.sync.aligned.m16n8k16.row.col.f32.bf16.bf16.f32 "
        "{%0,%1,%2,%3}, {%4,%5,%6,%7}, {%8,%9}, {%0,%1,%2,%3};"
        : "+f"(c[0]), "+f"(c[1]), "+f"(c[2]), "+f"(c[3])
        : "r"(a[0]), "r"(a[1]), "r"(a[2]), "r"(a[3]), "r"(b0), "r"(b1));
}
__device__ __forceinline__ float hsig(float x) {
    return fminf(fmaxf(0.2f * x + 0.5f, 0.f), 1.f);
}

// ================= HMMA compensated-bf16 implicit-conv GEMM (+fused LSTM gate) ====
// C[M,N] = gather3(Ahi+Alo)[M,K] @ (Bhi+Blo)[N,K]^T
// gateMode=0: +bias, store C.   gateMode=1: fused gate epilogue
//   (N gate-interleaved: col 4f+g, g in {i,f,c,o}); updates cst, writes hseq/hhi/hlo.
#define SROW  80
#define TILE  (128*SROW)   // 10240
#define BUFSZ (4*TILE)

__global__ __launch_bounds__(256) void mma_gemm_conv(
    const __nv_bfloat16* __restrict__ Ahi, const __nv_bfloat16* __restrict__ Alo,
    const __nv_bfloat16* __restrict__ Bhi, const __nv_bfloat16* __restrict__ Blo,
    const float* __restrict__ bias, float* __restrict__ C,
    const float* __restrict__ xg, float* __restrict__ cst,
    float* __restrict__ hseq,
    __nv_bfloat16* __restrict__ hhi, __nv_bfloat16* __restrict__ hlo,
    int M, int N, int K, int logCin, int gateMode)
{
    extern __shared__ char smem[];
    const uint32_t sb = smem_to_u32(smem);
    const int tid  = threadIdx.x;
    const int wid  = tid >> 5;
    const int lane = tid & 31;
    const int wm   = wid >> 1;
    const int wn   = wid & 1;
    const int m0   = blockIdx.y * 128;
    const int n0   = blockIdx.x * 128;
    const int Cin  = 1 << logCin;
    const int nk   = K >> 5;

    float acc[2][8][4];
    #pragma unroll
    for (int mt = 0; mt < 2; mt++)
        #pragma unroll
        for (int nt = 0; nt < 8; nt++)
            #pragma unroll
            for (int r = 0; r < 4; r++) acc[mt][nt][r] = 0.f;

    auto load_chunk = [&](int c, int buf) {
        const int k0  = c << 5;
        const int ks  = k0 >> logCin;
        const int ci0 = k0 & (Cin - 1);
        const uint32_t sbuf = sb + buf * BUFSZ;
        #pragma unroll
        for (int i = 0; i < 2; i++) {
            int idx = tid + (i << 8);
            int row = idx >> 2;
            int seg = idx & 3;
            int m  = m0 + row;
            int l  = m & (LDIM - 1);
            int ll = l + ks - 1;
            uint32_t sz = (ll >= 0 && ll < LDIM) ? 16u : 0u;
            int llc = ll < 0 ? 0 : (ll > LDIM - 1 ? LDIM - 1 : ll);
            size_t aoff = (size_t)(m - l + llc) * Cin + ci0 + seg * 8;
            uint32_t sa = sbuf + row * SROW + seg * 16;
            cp_async16(sa,            Ahi + aoff, sz);
            cp_async16(sa + TILE,     Alo + aoff, sz);
            size_t boff = (size_t)(n0 + row) * K + k0 + seg * 8;
            cp_async16(sa + 2 * TILE, Bhi + boff, 16u);
            cp_async16(sa + 3 * TILE, Blo + boff, 16u);
        }
    };

    const int a_row = lane & 15;
    const int a_k16 = (lane & 16) ? 16 : 0;
    const int b_row = (lane & 7) + ((lane & 16) ? 8 : 0);
    const int b_k16 = (lane & 8) ? 16 : 0;

    load_chunk(0, 0);
    CP_COMMIT();

    for (int c = 0; c < nk; c++) {
        if (c + 1 < nk) {
            load_chunk(c + 1, (c + 1) & 1);
            CP_COMMIT();
            CP_WAIT(1);
        } else {
            CP_WAIT(0);
        }
        __syncthreads();

        const uint32_t sbuf = sb + (c & 1) * BUFSZ;
        #pragma unroll
        for (int ks = 0; ks < 2; ks++) {
            uint32_t ah[2][4], al[2][4];
            #pragma unroll
            for (int mt = 0; mt < 2; mt++) {
                uint32_t ad = sbuf + (wm * 32 + mt * 16 + a_row) * SROW
                                   + ks * 32 + a_k16;
                LDSM_X4(ah[mt], ad);
                LDSM_X4(al[mt], ad + TILE);
            }
            #pragma unroll
            for (int n2 = 0; n2 < 4; n2++) {
                uint32_t bd = sbuf + 2 * TILE
                            + (wn * 64 + n2 * 16 + b_row) * SROW
                            + ks * 32 + b_k16;
                uint32_t bh[4], bl[4];
                LDSM_X4(bh, bd);
                LDSM_X4(bl, bd + TILE);
                #pragma unroll
                for (int mt = 0; mt < 2; mt++) {
                    mma16816(acc[mt][n2 * 2],     ah[mt], bh[0], bh[1]);
                    mma16816(acc[mt][n2 * 2],     ah[mt], bl[0], bl[1]);
                    mma16816(acc[mt][n2 * 2],     al[mt], bh[0], bh[1]);
                    mma16816(acc[mt][n2 * 2 + 1], ah[mt], bh[2], bh[3]);
                    mma16816(acc[mt][n2 * 2 + 1], ah[mt], bl[2], bl[3]);
                    mma16816(acc[mt][n2 * 2 + 1], al[mt], bh[2], bh[3]);
                }
            }
        }
        __syncthreads();
    }

    const int r0 = lane >> 2;
    const int q  = lane & 3;

    if (gateMode == 0) {
        const int cp = q * 2;
        #pragma unroll
        for (int mt = 0; mt < 2; mt++) {
            #pragma unroll
            for (int nt = 0; nt < 8; nt++) {
                int row = m0 + wm * 32 + mt * 16 + r0;
                int col = n0 + wn * 64 + nt * 8 + cp;
                float bx = 0.f, by = 0.f;
                if (bias) { bx = bias[col]; by = bias[col + 1]; }
                float2 v0 = make_float2(acc[mt][nt][0] + bx, acc[mt][nt][1] + by);
                float2 v1 = make_float2(acc[mt][nt][2] + bx, acc[mt][nt][3] + by);
                *reinterpret_cast<float2*>(C + (size_t)row * N + col)       = v0;
                *reinterpret_cast<float2*>(C + (size_t)(row + 8) * N + col) = v1;
            }
        }
    } else {
        // fused LSTM gate epilogue (gate-interleaved N: col 4f+g)
        const int F = N >> 2;
        const int rowAdd = (q & 1) ? 8 : 0;
        #pragma unroll
        for (int mt = 0; mt < 2; mt++) {
            #pragma unroll
            for (int nt = 0; nt < 8; nt++) {
                int colBase = n0 + wn * 64 + nt * 8;
                int myCol = colBase + q * 2;
                int row_lo = m0 + wm * 32 + mt * 16 + r0;
                float2 x0 = *reinterpret_cast<const float2*>(xg + (size_t)row_lo * N + myCol);
                float2 x1 = *reinterpret_cast<const float2*>(xg + (size_t)(row_lo + 8) * N + myCol);
                float a0 = acc[mt][nt][0] + x0.x;
                float a1 = acc[mt][nt][1] + x0.y;
                float a2 = acc[mt][nt][2] + x1.x;
                float a3 = acc[mt][nt][3] + x1.y;
                // even lane (q even): keeps row_lo, holds i,f; sends its row_hi i,f
                // odd  lane: keeps row_hi, holds c,o; sends its row_lo c,o
                float s0 = (q & 1) ? a0 : a2;
                float s1 = (q & 1) ? a1 : a3;
                float p0 = __shfl_xor_sync(0xffffffffu, s0, 1);
                float p1 = __shfl_xor_sync(0xffffffffu, s1, 1);
                float iv = (q & 1) ? p0 : a0;
                float fv = (q & 1) ? p1 : a1;
                float cv = (q & 1) ? a2 : p0;
                float ov = (q & 1) ? a3 : p1;
                int myRow = row_lo + rowAdd;
                int fidx = (colBase >> 2) + (q >> 1);
                size_t sidx = (size_t)myRow * F + fidx;
                float cn = hsig(fv) * cst[sidx] + hsig(iv) * fmaxf(cv, 0.f);
                cst[sidx] = cn;
                float hn = hsig(ov) * fmaxf(cn, 0.f);
                if (hseq) hseq[sidx] = hn;
                __nv_bfloat16 hi = __float2bfloat16(hn);
                hhi[sidx] = hi;
                hlo[sidx] = __float2bfloat16(hn - __bfloat162float(hi));
            }
        }
    }
}

// ===== weight convert: W[K,N] fp32 -> [N',K] bf16 hi/lo with gate interleave =====
__global__ void wconv_kernel(const float* __restrict__ W,
                             __nv_bfloat16* __restrict__ Bh, __nv_bfloat16* __restrict__ Bl,
                             int K, int N)
{
    int idx = blockIdx.x * blockDim.x + threadIdx.x;
    if (idx >= N * K) return;
    int np = idx / K, k = idx - np * K;          // np = permuted row (4f+g)
    int F = N >> 2;
    int n = (np & 3) * F + (np >> 2);            // original column
    float x = W[(size_t)k * N + n];
    __nv_bfloat16 hi = __float2bfloat16(x);
    Bh[idx] = hi;
    Bl[idx] = __float2bfloat16(x - __bfloat162float(hi));
}

// ===== bias permute: pb[4f+g] = b[g*F+f] =====
__global__ void permute_bias(const float* __restrict__ b, float* __restrict__ pb, int N)
{
    int idx = blockIdx.x * blockDim.x + threadIdx.x;
    if (idx >= N) return;
    int F = N >> 2;
    pb[idx] = b[(idx & 3) * F + (idx >> 2)];
}

// ===== permute Wx1 [3,256] fp32 -> gate-interleaved cols =====
__global__ void permute_wx1(const float* __restrict__ W, float* __restrict__ Wp)
{
    int idx = blockIdx.x * blockDim.x + threadIdx.x;
    if (idx >= 3 * 256) return;
    int k = idx >> 8, np = idx & 255;
    Wp[idx] = W[k * 256 + (np & 3) * 64 + (np >> 2)];
}

// ================= fp32 implicit GEMM (layer-1 input, K=3), T-major output ========
#define BM 128
#define BN 128
#define BK 8
__global__ __launch_bounds__(256) void gemm_conv_kernel(
    const float* __restrict__ A, const float* __restrict__ W,
    const float* __restrict__ bias, float* __restrict__ C,
    int M, int N, int K, int logCin)
{
    __shared__ float As[BK][BM];
    __shared__ float Bs[BK][BN];
    int tid = threadIdx.x;
    int m0 = blockIdx.y * BM;
    int n0 = blockIdx.x * BN;
    int tx = tid & 15, ty = tid >> 4;
    int a_row = tid >> 1;
    int a_col = (tid & 1) * 4;
    int b_k = tid >> 5;
    int b_n = (tid & 31) * 4;
    int Cin = 1 << logCin;
    float acc[8][8];
    #pragma unroll
    for (int i = 0; i < 8; i++)
        #pragma unroll
        for (int j = 0; j < 8; j++) acc[i][j] = 0.f;
    for (int k0 = 0; k0 < K; k0 += BK) {
        int m = m0 + a_row;
        #pragma unroll
        for (int i = 0; i < 4; i++) {
            int kk = k0 + a_col + i;
            float v = 0.f;
            if (m < M && kk < K) {
                int l = m & (LDIM - 1);
                int ks = kk >> logCin;
                int ci = kk - (ks << logCin);
                int ll = l + ks - 1;
                if (ll >= 0 && ll < LDIM)
                    v = A[(size_t)(m - l + ll) * Cin + ci];
            }
            As[a_col + i][a_row] = v;
        }
        {
            int kk = k0 + b_k;
            float4 v = make_float4(0.f, 0.f, 0.f, 0.f);
            if (kk < K && n0 + b_n + 3 < N)
                v = *reinterpret_cast<const float4*>(&W[(size_t)kk * N + n0 + b_n]);
            Bs[b_k][b_n] = v.x; Bs[b_k][b_n+1] = v.y; Bs[b_k][b_n+2] = v.z; Bs[b_k][b_n+3] = v.w;
        }
        __syncthreads();
        #pragma unroll
        for (int kk = 0; kk < BK; kk++) {
            float af[8], bf[8];
            #pragma unroll
            for (int i = 0; i < 8; i++) af[i] = As[kk][ty * 8 + i];
            #pragma unroll
            for (int j = 0; j < 8; j++) bf[j] = Bs[kk][tx * 8 + j];
            #pragma unroll
            for (int i = 0; i < 8; i++)
                #pragma unroll
                for (int j = 0; j < 8; j++) acc[i][j] += af[i] * bf[j];
        }
        __syncthreads();
    }
    #pragma unroll
    for (int i = 0; i < 8; i++) {
        int m = m0 + ty * 8 + i;
        if (m >= M) continue;
        // output row permute [B][T][L] -> [T][B][L]
        int l = m & (LDIM - 1);
        int bt = m >> LOG_L;
        int b = bt >> 5;          // /TDIM
        int t = bt & 31;
        int mp = ((t << 5) + b) * LDIM + l;
        #pragma unroll
        for (int j = 0; j < 8; j++) {
            int n = n0 + tx * 8 + j;
            if (n >= N) continue;
            float v = acc[i][j];
            if (bias) v += bias[n];
            C[(size_t)mp * N + n] = v;
        }
    }
}

// ================= BN (fp32 in place) =================
__global__ void bn_kernel(float* __restrict__ x, const float* __restrict__ gw,
                          const float* __restrict__ be, const float* __restrict__ mu,
                          const float* __restrict__ var, size_t total, int logC)
{
    size_t idx = (size_t)blockIdx.x * blockDim.x + threadIdx.x;
    if (idx >= total) return;
    int C = 1 << logC;
    int ch = (int)(idx & (size_t)(C - 1));
    x[idx] = (x[idx] - mu[ch]) * rsqrtf(var[ch] + 1e-3f) * gw[ch] + be[ch];
}

// ================= BN -> bf16 hi/lo convert =================
__global__ void bn_convert(const float* __restrict__ x, const float* __restrict__ gw,
                           const float* __restrict__ be, const float* __restrict__ mu,
                           const float* __restrict__ var,
                           __nv_bfloat16* __restrict__ oh, __nv_bfloat16* __restrict__ ol,
                           size_t total, int logC)
{
    size_t idx = (size_t)blockIdx.x * blockDim.x + threadIdx.x;
    if (idx >= total) return;
    int C = 1 << logC;
    int ch = (int)(idx & (size_t)(C - 1));
    float v = (x[idx] - mu[ch]) * rsqrtf(var[ch] + 1e-3f) * gw[ch] + be[ch];
    __nv_bfloat16 hi = __float2bfloat16(v);
    oh[idx] = hi;
    ol[idx] = __float2bfloat16(v - __bfloat162float(hi));
}

// ================= dense head (fp32, small) =================
__global__ __launch_bounds__(256) void fc_kernel(
    const float* __restrict__ A, const float* __restrict__ W,
    float* __restrict__ partial, int N, int K, int kchunk)
{
    __shared__ float As[32][33];
    int tid = threadIdx.x;
    int n0 = blockIdx.x * 64;
    int col = tid & 63;
    int rq = tid >> 6;
    int k0 = blockIdx.y * kchunk;
    int kend = min(K, k0 + kchunk);
    float acc[8];
    #pragma unroll
    for (int r = 0; r < 8; r++) acc[r] = 0.f;
    int a_m = tid >> 3;
    int a_k = (tid & 7) * 4;
    for (int kb = k0; kb < kend; kb += 32) {
        #pragma unroll
        for (int i = 0; i < 4; i++) {
            int kk = kb + a_k + i;
            As[a_m][a_k + i] = (kk < K) ? A[(size_t)a_m * K + kk] : 0.f;
        }
        __syncthreads();
        #pragma unroll
        for (int kk = 0; kk < 32; kk++) {
            float w = W[(size_t)(kb + kk) * N + n0 + col];
            #pragma unroll
            for (int r = 0; r < 8; r++) acc[r] += As[rq * 8 + r][kk] * w;
        }
        __syncthreads();
    }
    #pragma unroll
    for (int r = 0; r < 8; r++) {
        int m = rq * 8 + r;
        partial[((size_t)blockIdx.y * 32 + m) * N + n0 + col] = acc[r];
    }
}

__global__ void fc_reduce_relu(const float* __restrict__ partial,
                               const float* __restrict__ bias,
                               float* __restrict__ out, int N, int KS)
{
    int idx = blockIdx.x * blockDim.x + threadIdx.x;
    if (idx >= 32 * N) return;
    int m = idx / N, n = idx - m * N;
    float s = bias[n];
    for (int ks = 0; ks < KS; ks++)
        s += partial[((size_t)ks * 32 + m) * N + n];
    out[idx] = fmaxf(s, 0.f);
}

__global__ void fc3_softmax(const float* __restrict__ A, const float* __restrict__ W,
                            const float* __restrict__ bias, float* __restrict__ out)
{
    __shared__ float logits[32][5];
    int tid = threadIdx.x;
    int bm = tid >> 3, j = tid & 7;
    if (bm < 32 && j < 5) {
        float s = bias[j];
        for (int k = 0; k < 512; k++)
            s += A[bm * 512 + k] * W[k * 5 + j];
        logits[bm][j] = s;
    }
    __syncthreads();
    if (bm < 32 && j == 0) {
        float mx = logits[bm][0];
        for (int q = 1; q < 5; q++) mx = fmaxf(mx, logits[bm][q]);
        float e[5], sum = 0.f;
        for (int q = 0; q < 5; q++) { e[q] = expf(logits[bm][q] - mx); sum += e[q]; }
        for (int q = 0; q < 5; q++) out[bm * 5 + q] = e[q] / sum;
    }
}

// ================= host orchestration =================
extern "C" void kernel_launch(void* const* d_in, const int* in_sizes, int n_in,
                              void* d_out, int out_size)
{
    const float* x   = (const float*)d_in[0];
    const float* Wx1 = (const float*)d_in[1];
    const float* Wh1 = (const float*)d_in[2];
    const float* b1  = (const float*)d_in[3];
    const float* Wx2 = (const float*)d_in[4];
    const float* Wh2 = (const float*)d_in[5];
    const float* b2  = (const float*)d_in[6];
    const float* Wx3 = (const float*)d_in[7];
    const float* Wh3 = (const float*)d_in[8];
    const float* b3  = (const float*)d_in[9];
    const float* g1  = (const float*)d_in[10];
    const float* be1 = (const float*)d_in[11];
    const float* m1  = (const float*)d_in[12];
    const float* v1  = (const float*)d_in[13];
    const float* g2  = (const float*)d_in[14];
    const float* be2 = (const float*)d_in[15];
    const float* m2  = (const float*)d_in[16];
    const float* v2  = (const float*)d_in[17];
    const float* g3  = (const float*)d_in[18];
    const float* be3 = (const float*)d_in[19];
    const float* m3  = (const float*)d_in[20];
    const float* v3  = (const float*)d_in[21];
    const float* D1  = (const float*)d_in[22];
    const float* db1 = (const float*)d_in[23];
    const float* D2  = (const float*)d_in[24];
    const float* db2 = (const float*)d_in[25];
    const float* D3  = (const float*)d_in[26];
    const float* db3 = (const float*)d_in[27];
    float* out = (float*)d_out;

    float *xg1, *xg2, *xg3, *h1, *h2, *hst, *cst, *prt, *a1, *a2;
    float *pb1, *pb2, *pb3, *wx1p;
    __nv_bfloat16 *hhi, *hlo, *bn1h, *bn1l, *bn2h, *bn2l;
    __nv_bfloat16 *wh1h, *wh1l, *wx2h, *wx2l, *wh2h, *wh2l, *wx3h, *wx3l, *wh3h, *wh3l;
    cudaGetSymbolAddress((void**)&xg1, g_xg1);
    cudaGetSymbolAddress((void**)&xg2, g_xg2);
    cudaGetSymbolAddress((void**)&xg3, g_xg3);
    cudaGetSymbolAddress((void**)&h1,  g_h1);
    cudaGetSymbolAddress((void**)&h2,  g_h2);
    cudaGetSymbolAddress((void**)&hst, g_hst);
    cudaGetSymbolAddress((void**)&cst, g_cst);
    cudaGetSymbolAddress((void**)&prt, g_prt);
    cudaGetSymbolAddress((void**)&a1,  g_a1);
    cudaGetSymbolAddress((void**)&a2,  g_a2);
    cudaGetSymbolAddress((void**)&pb1, g_pb1);
    cudaGetSymbolAddress((void**)&pb2, g_pb2);
    cudaGetSymbolAddress((void**)&pb3, g_pb3);
    cudaGetSymbolAddress((void**)&wx1p, g_wx1p);
    cudaGetSymbolAddress((void**)&hhi, g_hhi);
    cudaGetSymbolAddress((void**)&hlo, g_hlo);
    cudaGetSymbolAddress((void**)&bn1h, g_bn1h);
    cudaGetSymbolAddress((void**)&bn1l, g_bn1l);
    cudaGetSymbolAddress((void**)&bn2h, g_bn2h);
    cudaGetSymbolAddress((void**)&bn2l, g_bn2l);
    cudaGetSymbolAddress((void**)&wh1h, g_wh1h); cudaGetSymbolAddress((void**)&wh1l, g_wh1l);
    cudaGetSymbolAddress((void**)&wx2h, g_wx2h); cudaGetSymbolAddress((void**)&wx2l, g_wx2l);
    cudaGetSymbolAddress((void**)&wh2h, g_wh2h); cudaGetSymbolAddress((void**)&wh2l, g_wh2l);
    cudaGetSymbolAddress((void**)&wx3h, g_wx3h); cudaGetSymbolAddress((void**)&wx3l, g_wx3l);
    cudaGetSymbolAddress((void**)&wh3h, g_wh3h); cudaGetSymbolAddress((void**)&wh3l, g_wh3l);

    const int Mall = BDIM * TDIM * LDIM;   // 131072
    const int Mst  = BDIM * LDIM;          // 4096
    const int SMEM_MMA = 2 * BUFSZ;        // 81920
    cudaFuncSetAttribute(mma_gemm_conv, cudaFuncAttributeMaxDynamicSharedMemorySize, SMEM_MMA);
    dim3 blk(256);

    // ---- weight/bias conversions (gate-interleaved) ----
    wconv_kernel<<<(256*192  + 255)/256, 256>>>(Wh1, wh1h, wh1l, 192, 256);
    wconv_kernel<<<(512*192  + 255)/256, 256>>>(Wx2, wx2h, wx2l, 192, 512);
    wconv_kernel<<<(512*384  + 255)/256, 256>>>(Wh2, wh2h, wh2l, 384, 512);
    wconv_kernel<<<(1024*384 + 255)/256, 256>>>(Wx3, wx3h, wx3l, 384, 1024);
    wconv_kernel<<<(1024*768 + 255)/256, 256>>>(Wh3, wh3h, wh3l, 768, 1024);
    permute_bias<<<1, 256>>>(b1, pb1, 256);
    permute_bias<<<2, 256>>>(b2, pb2, 512);
    permute_bias<<<4, 256>>>(b3, pb3, 1024);
    permute_wx1<<<3, 256>>>(Wx1, wx1p);

    // ================= Layer 1 =================
    gemm_conv_kernel<<<dim3(2, Mall / BM), blk>>>(x, wx1p, pb1, xg1, Mall, 256, 3, 0);
    cudaMemsetAsync(hhi, 0, (size_t)Mst * 64 * sizeof(__nv_bfloat16));
    cudaMemsetAsync(hlo, 0, (size_t)Mst * 64 * sizeof(__nv_bfloat16));
    cudaMemsetAsync(cst, 0, (size_t)Mst * 64 * sizeof(float));
    for (int t = 0; t < TDIM; t++) {
        mma_gemm_conv<<<dim3(2, Mst / 128), blk, SMEM_MMA>>>(
            hhi, hlo, wh1h, wh1l, nullptr, nullptr,
            xg1 + (size_t)t * Mst * 256, cst, h1 + (size_t)t * Mst * 64, hhi, hlo,
            Mst, 256, 192, 6, 1);
    }
    {
        size_t tot = (size_t)TDIM * Mst * 64;
        bn_convert<<<(int)((tot + 255) / 256), 256>>>(h1, g1, be1, m1, v1, bn1h, bn1l, tot, 6);
    }

    // ================= Layer 2 =================
    mma_gemm_conv<<<dim3(4, Mall / 128), blk, SMEM_MMA>>>(
        bn1h, bn1l, wx2h, wx2l, pb2, xg2,
        nullptr, nullptr, nullptr, nullptr, nullptr,
        Mall, 512, 192, 6, 0);
    cudaMemsetAsync(hhi, 0, (size_t)Mst * 128 * sizeof(__nv_bfloat16));
    cudaMemsetAsync(hlo, 0, (size_t)Mst * 128 * sizeof(__nv_bfloat16));
    cudaMemsetAsync(cst, 0, (size_t)Mst * 128 * sizeof(float));
    for (int t = 0; t < TDIM; t++) {
        mma_gemm_conv<<<dim3(4, Mst / 128), blk, SMEM_MMA>>>(
            hhi, hlo, wh2h, wh2l, nullptr, nullptr,
            xg2 + (size_t)t * Mst * 512, cst, h2 + (size_t)t * Mst * 128, hhi, hlo,
            Mst, 512, 384, 7, 1);
    }
    {
        size_t tot = (size_t)TDIM * Mst * 128;
        bn_convert<<<(int)((tot + 255) / 256), 256>>>(h2, g2, be2, m2, v2, bn2h, bn2l, tot, 7);
    }

    // ================= Layer 3 =================
    mma_gemm_conv<<<dim3(8, Mall / 128), blk, SMEM_MMA>>>(
        bn2h, bn2l, wx3h, wx3l, pb3, xg3,
        nullptr, nullptr, nullptr, nullptr, nullptr,
        Mall, 1024, 384, 7, 0);
    cudaMemsetAsync(hhi, 0, (size_t)Mst * 256 * sizeof(__nv_bfloat16));
    cudaMemsetAsync(hlo, 0, (size_t)Mst * 256 * sizeof(__nv_bfloat16));
    cudaMemsetAsync(cst, 0, (size_t)Mst * 256 * sizeof(float));
    for (int t = 0; t < TDIM; t++) {
        mma_gemm_conv<<<dim3(8, Mst / 128), blk, SMEM_MMA>>>(
            hhi, hlo, wh3h, wh3l, nullptr, nullptr,
            xg3 + (size_t)t * Mst * 1024, cst, hst, hhi, hlo,
            Mst, 1024, 768, 8, 1);
    }
    {
        size_t tot = (size_t)Mst * 256;
        bn_kernel<<<(int)((tot + 255) / 256), 256>>>(hst, g3, be3, m3, v3, tot, 8);
    }

    // ================= Dense head =================
    fc_kernel<<<dim3(1024 / 64, 8), blk>>>(hst, D1, prt, 1024, 32768, 4096);
    fc_reduce_relu<<<(32 * 1024 + 255) / 256, 256>>>(prt, db1, a1, 1024, 8);
    fc_kernel<<<dim3(512 / 64, 2), blk>>>(a1, D2, prt, 512, 1024, 512);
    fc_reduce_relu<<<(32 * 512 + 255) / 256, 256>>>(prt, db2, a2, 512, 2);
    fc3_softmax<<<1, 256>>>(a2, D3, db3, out);
}

// round 14
// speedup vs baseline: 1.1017x; 1.1017x over previous
#include <cuda_runtime.h>
#include <cuda_bf16.h>
#include <math.h>
#include <cstdint>

#define BDIM 32
#define TDIM 32
#define LDIM 128
#define LOG_L 7

// ================= scratch (static device globals) =================
__device__ float g_xg1[(size_t)TDIM*BDIM*LDIM*256];   // [T][B][L][4F1] (gate-interleaved)
__device__ float g_xg2[(size_t)TDIM*BDIM*LDIM*512];   // [T][B][L][4F2]
__device__ float g_xg3[(size_t)TDIM*BDIM*LDIM*1024];  // [T][B][L][4F3]
__device__ float g_h1 [(size_t)TDIM*BDIM*LDIM*64];    // [T][B][L][F1]
__device__ float g_h2 [(size_t)TDIM*BDIM*LDIM*128];   // [T][B][L][F2]
__device__ float g_hst[(size_t)BDIM*LDIM*256];
__device__ float g_cst[(size_t)BDIM*LDIM*256];
__device__ float g_prt[(size_t)8*BDIM*1024];
__device__ float g_a1 [(size_t)BDIM*1024];
__device__ float g_a2 [(size_t)BDIM*512];
__device__ float g_pb1[256], g_pb2[512], g_pb3[1024];
__device__ float g_wx1p[3*256];

// bf16 hi/lo activations
__device__ __nv_bfloat16 g_hhi[(size_t)BDIM*LDIM*256];
__device__ __nv_bfloat16 g_hlo[(size_t)BDIM*LDIM*256];
__device__ __nv_bfloat16 g_bn1h[(size_t)TDIM*BDIM*LDIM*64];
__device__ __nv_bfloat16 g_bn1l[(size_t)TDIM*BDIM*LDIM*64];
__device__ __nv_bfloat16 g_bn2h[(size_t)TDIM*BDIM*LDIM*128];
__device__ __nv_bfloat16 g_bn2l[(size_t)TDIM*BDIM*LDIM*128];

// bf16 hi/lo weights, [N,K] layout, N gate-interleaved (n' = 4f+g)
__device__ __nv_bfloat16 g_wh1h[256*192],  g_wh1l[256*192];
__device__ __nv_bfloat16 g_wx2h[512*192],  g_wx2l[512*192];
__device__ __nv_bfloat16 g_wh2h[512*384],  g_wh2l[512*384];
__device__ __nv_bfloat16 g_wx3h[1024*384], g_wx3l[1024*384];
__device__ __nv_bfloat16 g_wh3h[1024*768], g_wh3l[1024*768];

// ================= helpers =================
__device__ __forceinline__ uint32_t smem_to_u32(const void* p) {
    uint32_t a;
    asm("{ .reg .u64 t; cvta.to.shared.u64 t, %1; cvt.u32.u64 %0, t; }" : "=r"(a) : "l"(p));
    return a;
}
__device__ __forceinline__ void cp_async16(uint32_t saddr, const void* gaddr, uint32_t sz) {
    asm volatile("cp.async.cg.shared.global [%0], [%1], 16, %2;"
                 :: "r"(saddr), "l"(gaddr), "r"(sz));
}
#define CP_COMMIT() asm volatile("cp.async.commit_group;" ::: "memory")
#define CP_WAIT(n)  asm volatile("cp.async.wait_group %0;" :: "n"(n) : "memory")
#define LDSM_X4(r, addr) \
    asm volatile("ldmatrix.sync.aligned.m8n8.x4.shared.b16 {%0,%1,%2,%3}, [%4];" \
        : "=r"((r)[0]), "=r"((r)[1]), "=r"((r)[2]), "=r"((r)[3]) : "r"(addr))

__device__ __forceinline__ void mma16816(float* c, const uint32_t* a,
                                         uint32_t b0, uint32_t b1) {
    asm volatile("mma.sync.aligned.m16n8k16.row.col.f32.bf16.bf16.f32 "
        "{%0,%1,%2,%3}, {%4,%5,%6,%7}, {%8,%9}, {%0,%1,%2,%3};"
        : "+f"(c[0]), "+f"(c[1]), "+f"(c[2]), "+f"(c[3])
        : "r"(a[0]), "r"(a[1]), "r"(a[2]), "r"(a[3]), "r"(b0), "r"(b1));
}
__device__ __forceinline__ float hsig(float x) {
    return fminf(fmaxf(0.2f * x + 0.5f, 0.f), 1.f);
}

// ================= HMMA compensated-bf16 implicit-conv GEMM (+fused LSTM gate) ====
// C[M,N] = gather3(Ahi+Alo)[M,K] @ (Bhi+Blo)[N,K]^T
// gateMode=0: +bias, store C.
// gateMode=1: gate epilogue staged through SMEM for coalescing
//   (N gate-interleaved: col 4f+g, g in {i,f,c,o}); updates cst, writes hseq/hhi/hlo.
#define SROW  80
#define TILE  (128*SROW)   // 10240
#define BUFSZ (4*TILE)
#define STROW 132          // fp32 staging row stride (floats)

__global__ __launch_bounds__(256) void mma_gemm_conv(
    const __nv_bfloat16* __restrict__ Ahi, const __nv_bfloat16* __restrict__ Alo,
    const __nv_bfloat16* __restrict__ Bhi, const __nv_bfloat16* __restrict__ Blo,
    const float* __restrict__ bias, float* __restrict__ C,
    const float* __restrict__ xg, float* __restrict__ cst,
    float* __restrict__ hseq,
    __nv_bfloat16* __restrict__ hhi, __nv_bfloat16* __restrict__ hlo,
    int M, int N, int K, int logCin, int gateMode)
{
    extern __shared__ char smem[];
    const uint32_t sb = smem_to_u32(smem);
    const int tid  = threadIdx.x;
    const int wid  = tid >> 5;
    const int lane = tid & 31;
    const int wm   = wid >> 1;
    const int wn   = wid & 1;
    const int m0   = blockIdx.y * 128;
    const int n0   = blockIdx.x * 128;
    const int Cin  = 1 << logCin;
    const int nk   = K >> 5;

    float acc[2][8][4];
    #pragma unroll
    for (int mt = 0; mt < 2; mt++)
        #pragma unroll
        for (int nt = 0; nt < 8; nt++)
            #pragma unroll
            for (int r = 0; r < 4; r++) acc[mt][nt][r] = 0.f;

    auto load_chunk = [&](int c, int buf) {
        const int k0  = c << 5;
        const int ks  = k0 >> logCin;
        const int ci0 = k0 & (Cin - 1);
        const uint32_t sbuf = sb + buf * BUFSZ;
        #pragma unroll
        for (int i = 0; i < 2; i++) {
            int idx = tid + (i << 8);
            int row = idx >> 2;
            int seg = idx & 3;
            int m  = m0 + row;
            int l  = m & (LDIM - 1);
            int ll = l + ks - 1;
            uint32_t sz = (ll >= 0 && ll < LDIM) ? 16u : 0u;
            int llc = ll < 0 ? 0 : (ll > LDIM - 1 ? LDIM - 1 : ll);
            size_t aoff = (size_t)(m - l + llc) * Cin + ci0 + seg * 8;
            uint32_t sa = sbuf + row * SROW + seg * 16;
            cp_async16(sa,            Ahi + aoff, sz);
            cp_async16(sa + TILE,     Alo + aoff, sz);
            size_t boff = (size_t)(n0 + row) * K + k0 + seg * 8;
            cp_async16(sa + 2 * TILE, Bhi + boff, 16u);
            cp_async16(sa + 3 * TILE, Blo + boff, 16u);
        }
    };

    const int a_row = lane & 15;
    const int a_k16 = (lane & 16) ? 16 : 0;
    const int b_row = (lane & 7) + ((lane & 16) ? 8 : 0);
    const int b_k16 = (lane & 8) ? 16 : 0;

    load_chunk(0, 0);
    CP_COMMIT();

    for (int c = 0; c < nk; c++) {
        if (c + 1 < nk) {
            load_chunk(c + 1, (c + 1) & 1);
            CP_COMMIT();
            CP_WAIT(1);
        } else {
            CP_WAIT(0);
        }
        __syncthreads();

        const uint32_t sbuf = sb + (c & 1) * BUFSZ;
        #pragma unroll
        for (int ks = 0; ks < 2; ks++) {
            uint32_t ah[2][4], al[2][4];
            #pragma unroll
            for (int mt = 0; mt < 2; mt++) {
                uint32_t ad = sbuf + (wm * 32 + mt * 16 + a_row) * SROW
                                   + ks * 32 + a_k16;
                LDSM_X4(ah[mt], ad);
                LDSM_X4(al[mt], ad + TILE);
            }
            #pragma unroll
            for (int n2 = 0; n2 < 4; n2++) {
                uint32_t bd = sbuf + 2 * TILE
                            + (wn * 64 + n2 * 16 + b_row) * SROW
                            + ks * 32 + b_k16;
                uint32_t bh[4], bl[4];
                LDSM_X4(bh, bd);
                LDSM_X4(bl, bd + TILE);
                #pragma unroll
                for (int mt = 0; mt < 2; mt++) {
                    mma16816(acc[mt][n2 * 2],     ah[mt], bh[0], bh[1]);
                    mma16816(acc[mt][n2 * 2],     ah[mt], bl[0], bl[1]);
                    mma16816(acc[mt][n2 * 2],     al[mt], bh[0], bh[1]);
                    mma16816(acc[mt][n2 * 2 + 1], ah[mt], bh[2], bh[3]);
                    mma16816(acc[mt][n2 * 2 + 1], ah[mt], bl[2], bl[3]);
                    mma16816(acc[mt][n2 * 2 + 1], al[mt], bh[2], bh[3]);
                }
            }
        }
        __syncthreads();
    }

    const int r0 = lane >> 2;
    const int q  = lane & 3;

    if (gateMode == 0) {
        const int cp = q * 2;
        #pragma unroll
        for (int mt = 0; mt < 2; mt++) {
            #pragma unroll
            for (int nt = 0; nt < 8; nt++) {
                int row = m0 + wm * 32 + mt * 16 + r0;
                int col = n0 + wn * 64 + nt * 8 + cp;
                float bx = 0.f, by = 0.f;
                if (bias) { bx = bias[col]; by = bias[col + 1]; }
                float2 v0 = make_float2(acc[mt][nt][0] + bx, acc[mt][nt][1] + by);
                float2 v1 = make_float2(acc[mt][nt][2] + bx, acc[mt][nt][3] + by);
                *reinterpret_cast<float2*>(C + (size_t)row * N + col)       = v0;
                *reinterpret_cast<float2*>(C + (size_t)(row + 8) * N + col) = v1;
            }
        }
    } else {
        // ---- stage accumulators into SMEM (fp32, row stride STROW) ----
        float* st = reinterpret_cast<float*>(smem);
        #pragma unroll
        for (int mt = 0; mt < 2; mt++) {
            #pragma unroll
            for (int nt = 0; nt < 8; nt++) {
                int row_l = wm * 32 + mt * 16 + r0;
                int col_l = wn * 64 + nt * 8 + q * 2;
                *reinterpret_cast<float2*>(&st[row_l * STROW + col_l]) =
                    make_float2(acc[mt][nt][0], acc[mt][nt][1]);
                *reinterpret_cast<float2*>(&st[(row_l + 8) * STROW + col_l]) =
                    make_float2(acc[mt][nt][2], acc[mt][nt][3]);
            }
        }
        __syncthreads();
        // ---- coalesced gate pass: warp = row, lanes sweep 32 features ----
        const int F = N >> 2;
        const int f0 = n0 >> 2;
        #pragma unroll
        for (int i = 0; i < 16; i++) {
            int e   = tid + (i << 8);        // 0..4095
            int row = e >> 5;                // 0..127
            int f   = e & 31;                // 0..31
            float4 g4 = *reinterpret_cast<const float4*>(&st[row * STROW + 4 * f]);
            int m = m0 + row;
            float4 x4 = *reinterpret_cast<const float4*>(xg + (size_t)m * N + n0 + 4 * f);
            float iv = g4.x + x4.x;
            float fv = g4.y + x4.y;
            float cv = g4.z + x4.z;
            float ov = g4.w + x4.w;
            size_t sidx = (size_t)m * F + f0 + f;
            float cn = hsig(fv) * cst[sidx] + hsig(iv) * fmaxf(cv, 0.f);
            cst[sidx] = cn;
            float hn = hsig(ov) * fmaxf(cn, 0.f);
            hseq[sidx] = hn;
            __nv_bfloat16 hi = __float2bfloat16(hn);
            hhi[sidx] = hi;
            hlo[sidx] = __float2bfloat16(hn - __bfloat162float(hi));
        }
    }
}

// ===== t=0 gate (h=c=0): c = hsig(i)*relu(cg); also initializes cst/h buffers =====
__global__ void gate0_kernel(const float4* __restrict__ xg, float* __restrict__ cst,
                             float* __restrict__ hseq,
                             __nv_bfloat16* __restrict__ hhi,
                             __nv_bfloat16* __restrict__ hlo, int total)
{
    int idx = blockIdx.x * blockDim.x + threadIdx.x;
    if (idx >= total) return;
    float4 x4 = xg[idx];
    float cn = hsig(x4.x) * fmaxf(x4.z, 0.f);
    cst[idx] = cn;
    float hn = hsig(x4.w) * fmaxf(cn, 0.f);
    hseq[idx] = hn;
    __nv_bfloat16 hi = __float2bfloat16(hn);
    hhi[idx] = hi;
    hlo[idx] = __float2bfloat16(hn - __bfloat162float(hi));
}

// ===== weight convert: W[K,N] fp32 -> [N',K] bf16 hi/lo with gate interleave =====
__global__ void wconv_kernel(const float* __restrict__ W,
                             __nv_bfloat16* __restrict__ Bh, __nv_bfloat16* __restrict__ Bl,
                             int K, int N)
{
    int idx = blockIdx.x * blockDim.x + threadIdx.x;
    if (idx >= N * K) return;
    int np = idx / K, k = idx - np * K;
    int F = N >> 2;
    int n = (np & 3) * F + (np >> 2);
    float x = W[(size_t)k * N + n];
    __nv_bfloat16 hi = __float2bfloat16(x);
    Bh[idx] = hi;
    Bl[idx] = __float2bfloat16(x - __bfloat162float(hi));
}

// ===== bias permute: pb[4f+g] = b[g*F+f] =====
__global__ void permute_bias(const float* __restrict__ b, float* __restrict__ pb, int N)
{
    int idx = blockIdx.x * blockDim.x + threadIdx.x;
    if (idx >= N) return;
    int F = N >> 2;
    pb[idx] = b[(idx & 3) * F + (idx >> 2)];
}

// ===== permute Wx1 [3,256] fp32 -> gate-interleaved cols =====
__global__ void permute_wx1(const float* __restrict__ W, float* __restrict__ Wp)
{
    int idx = blockIdx.x * blockDim.x + threadIdx.x;
    if (idx >= 3 * 256) return;
    int k = idx >> 8, np = idx & 255;
    Wp[idx] = W[k * 256 + (np & 3) * 64 + (np >> 2)];
}

// ================= fp32 implicit GEMM (layer-1 input, K=3), T-major output ========
#define BM 128
#define BN 128
#define BK 8
__global__ __launch_bounds__(256) void gemm_conv_kernel(
    const float* __restrict__ A, const float* __restrict__ W,
    const float* __restrict__ bias, float* __restrict__ C,
    int M, int N, int K, int logCin)
{
    __shared__ float As[BK][BM];
    __shared__ float Bs[BK][BN];
    int tid = threadIdx.x;
    int m0 = blockIdx.y * BM;
    int n0 = blockIdx.x * BN;
    int tx = tid & 15, ty = tid >> 4;
    int a_row = tid >> 1;
    int a_col = (tid & 1) * 4;
    int b_k = tid >> 5;
    int b_n = (tid & 31) * 4;
    int Cin = 1 << logCin;
    float acc[8][8];
    #pragma unroll
    for (int i = 0; i < 8; i++)
        #pragma unroll
        for (int j = 0; j < 8; j++) acc[i][j] = 0.f;
    for (int k0 = 0; k0 < K; k0 += BK) {
        int m = m0 + a_row;
        #pragma unroll
        for (int i = 0; i < 4; i++) {
            int kk = k0 + a_col + i;
            float v = 0.f;
            if (m < M && kk < K) {
                int l = m & (LDIM - 1);
                int ks = kk >> logCin;
                int ci = kk - (ks << logCin);
                int ll = l + ks - 1;
                if (ll >= 0 && ll < LDIM)
                    v = A[(size_t)(m - l + ll) * Cin + ci];
            }
            As[a_col + i][a_row] = v;
        }
        {
            int kk = k0 + b_k;
            float4 v = make_float4(0.f, 0.f, 0.f, 0.f);
            if (kk < K && n0 + b_n + 3 < N)
                v = *reinterpret_cast<const float4*>(&W[(size_t)kk * N + n0 + b_n]);
            Bs[b_k][b_n] = v.x; Bs[b_k][b_n+1] = v.y; Bs[b_k][b_n+2] = v.z; Bs[b_k][b_n+3] = v.w;
        }
        __syncthreads();
        #pragma unroll
        for (int kk = 0; kk < BK; kk++) {
            float af[8], bf[8];
            #pragma unroll
            for (int i = 0; i < 8; i++) af[i] = As[kk][ty * 8 + i];
            #pragma unroll
            for (int j = 0; j < 8; j++) bf[j] = Bs[kk][tx * 8 + j];
            #pragma unroll
            for (int i = 0; i < 8; i++)
                #pragma unroll
                for (int j = 0; j < 8; j++) acc[i][j] += af[i] * bf[j];
        }
        __syncthreads();
    }
    #pragma unroll
    for (int i = 0; i < 8; i++) {
        int m = m0 + ty * 8 + i;
        if (m >= M) continue;
        // output row permute [B][T][L] -> [T][B][L]
        int l = m & (LDIM - 1);
        int bt = m >> LOG_L;
        int b = bt >> 5;
        int t = bt & 31;
        int mp = ((t << 5) + b) * LDIM + l;
        #pragma unroll
        for (int j = 0; j < 8; j++) {
            int n = n0 + tx * 8 + j;
            if (n >= N) continue;
            float v = acc[i][j];
            if (bias) v += bias[n];
            C[(size_t)mp * N + n] = v;
        }
    }
}

// ================= BN (fp32 in place) =================
__global__ void bn_kernel(float* __restrict__ x, const float* __restrict__ gw,
                          const float* __restrict__ be, const float* __restrict__ mu,
                          const float* __restrict__ var, size_t total, int logC)
{
    size_t idx = (size_t)blockIdx.x * blockDim.x + threadIdx.x;
    if (idx >= total) return;
    int C = 1 << logC;
    int ch = (int)(idx & (size_t)(C - 1));
    x[idx] = (x[idx] - mu[ch]) * rsqrtf(var[ch] + 1e-3f) * gw[ch] + be[ch];
}

// ================= BN -> bf16 hi/lo convert =================
__global__ void bn_convert(const float* __restrict__ x, const float* __restrict__ gw,
                           const float* __restrict__ be, const float* __restrict__ mu,
                           const float* __restrict__ var,
                           __nv_bfloat16* __restrict__ oh, __nv_bfloat16* __restrict__ ol,
                           size_t total, int logC)
{
    size_t idx = (size_t)blockIdx.x * blockDim.x + threadIdx.x;
    if (idx >= total) return;
    int C = 1 << logC;
    int ch = (int)(idx & (size_t)(C - 1));
    float v = (x[idx] - mu[ch]) * rsqrtf(var[ch] + 1e-3f) * gw[ch] + be[ch];
    __nv_bfloat16 hi = __float2bfloat16(v);
    oh[idx] = hi;
    ol[idx] = __float2bfloat16(v - __bfloat162float(hi));
}

// ================= dense head (fp32, small) =================
__global__ __launch_bounds__(256) void fc_kernel(
    const float* __restrict__ A, const float* __restrict__ W,
    float* __restrict__ partial, int N, int K, int kchunk)
{
    __shared__ float As[32][33];
    int tid = threadIdx.x;
    int n0 = blockIdx.x * 64;
    int col = tid & 63;
    int rq = tid >> 6;
    int k0 = blockIdx.y * kchunk;
    int kend = min(K, k0 + kchunk);
    float acc[8];
    #pragma unroll
    for (int r = 0; r < 8; r++) acc[r] = 0.f;
    int a_m = tid >> 3;
    int a_k = (tid & 7) * 4;
    for (int kb = k0; kb < kend; kb += 32) {
        #pragma unroll
        for (int i = 0; i < 4; i++) {
            int kk = kb + a_k + i;
            As[a_m][a_k + i] = (kk < K) ? A[(size_t)a_m * K + kk] : 0.f;
        }
        __syncthreads();
        #pragma unroll
        for (int kk = 0; kk < 32; kk++) {
            float w = W[(size_t)(kb + kk) * N + n0 + col];
            #pragma unroll
            for (int r = 0; r < 8; r++) acc[r] += As[rq * 8 + r][kk] * w;
        }
        __syncthreads();
    }
    #pragma unroll
    for (int r = 0; r < 8; r++) {
        int m = rq * 8 + r;
        partial[((size_t)blockIdx.y * 32 + m) * N + n0 + col] = acc[r];
    }
}

__global__ void fc_reduce_relu(const float* __restrict__ partial,
                               const float* __restrict__ bias,
                               float* __restrict__ out, int N, int KS)
{
    int idx = blockIdx.x * blockDim.x + threadIdx.x;
    if (idx >= 32 * N) return;
    int m = idx / N, n = idx - m * N;
    float s = bias[n];
    for (int ks = 0; ks < KS; ks++)
        s += partial[((size_t)ks * 32 + m) * N + n];
    out[idx] = fmaxf(s, 0.f);
}

__global__ void fc3_softmax(const float* __restrict__ A, const float* __restrict__ W,
                            const float* __restrict__ bias, float* __restrict__ out)
{
    __shared__ float logits[32][5];
    int tid = threadIdx.x;
    int bm = tid >> 3, j = tid & 7;
    if (bm < 32 && j < 5) {
        float s = bias[j];
        for (int k = 0; k < 512; k++)
            s += A[bm * 512 + k] * W[k * 5 + j];
        logits[bm][j] = s;
    }
    __syncthreads();
    if (bm < 32 && j == 0) {
        float mx = logits[bm][0];
        for (int q = 1; q < 5; q++) mx = fmaxf(mx, logits[bm][q]);
        float e[5], sum = 0.f;
        for (int q = 0; q < 5; q++) { e[q] = expf(logits[bm][q] - mx); sum += e[q]; }
        for (int q = 0; q < 5; q++) out[bm * 5 + q] = e[q] / sum;
    }
}

// ================= host orchestration =================
extern "C" void kernel_launch(void* const* d_in, const int* in_sizes, int n_in,
                              void* d_out, int out_size)
{
    const float* x   = (const float*)d_in[0];
    const float* Wx1 = (const float*)d_in[1];
    const float* Wh1 = (const float*)d_in[2];
    const float* b1  = (const float*)d_in[3];
    const float* Wx2 = (const float*)d_in[4];
    const float* Wh2 = (const float*)d_in[5];
    const float* b2  = (const float*)d_in[6];
    const float* Wx3 = (const float*)d_in[7];
    const float* Wh3 = (const float*)d_in[8];
    const float* b3  = (const float*)d_in[9];
    const float* g1  = (const float*)d_in[10];
    const float* be1 = (const float*)d_in[11];
    const float* m1  = (const float*)d_in[12];
    const float* v1  = (const float*)d_in[13];
    const float* g2  = (const float*)d_in[14];
    const float* be2 = (const float*)d_in[15];
    const float* m2  = (const float*)d_in[16];
    const float* v2  = (const float*)d_in[17];
    const float* g3  = (const float*)d_in[18];
    const float* be3 = (const float*)d_in[19];
    const float* m3  = (const float*)d_in[20];
    const float* v3  = (const float*)d_in[21];
    const float* D1  = (const float*)d_in[22];
    const float* db1 = (const float*)d_in[23];
    const float* D2  = (const float*)d_in[24];
    const float* db2 = (const float*)d_in[25];
    const float* D3  = (const float*)d_in[26];
    const float* db3 = (const float*)d_in[27];
    float* out = (float*)d_out;

    float *xg1, *xg2, *xg3, *h1, *h2, *hst, *cst, *prt, *a1, *a2;
    float *pb1, *pb2, *pb3, *wx1p;
    __nv_bfloat16 *hhi, *hlo, *bn1h, *bn1l, *bn2h, *bn2l;
    __nv_bfloat16 *wh1h, *wh1l, *wx2h, *wx2l, *wh2h, *wh2l, *wx3h, *wx3l, *wh3h, *wh3l;
    cudaGetSymbolAddress((void**)&xg1, g_xg1);
    cudaGetSymbolAddress((void**)&xg2, g_xg2);
    cudaGetSymbolAddress((void**)&xg3, g_xg3);
    cudaGetSymbolAddress((void**)&h1,  g_h1);
    cudaGetSymbolAddress((void**)&h2,  g_h2);
    cudaGetSymbolAddress((void**)&hst, g_hst);
    cudaGetSymbolAddress((void**)&cst, g_cst);
    cudaGetSymbolAddress((void**)&prt, g_prt);
    cudaGetSymbolAddress((void**)&a1,  g_a1);
    cudaGetSymbolAddress((void**)&a2,  g_a2);
    cudaGetSymbolAddress((void**)&pb1, g_pb1);
    cudaGetSymbolAddress((void**)&pb2, g_pb2);
    cudaGetSymbolAddress((void**)&pb3, g_pb3);
    cudaGetSymbolAddress((void**)&wx1p, g_wx1p);
    cudaGetSymbolAddress((void**)&hhi, g_hhi);
    cudaGetSymbolAddress((void**)&hlo, g_hlo);
    cudaGetSymbolAddress((void**)&bn1h, g_bn1h);
    cudaGetSymbolAddress((void**)&bn1l, g_bn1l);
    cudaGetSymbolAddress((void**)&bn2h, g_bn2h);
    cudaGetSymbolAddress((void**)&bn2l, g_bn2l);
    cudaGetSymbolAddress((void**)&wh1h, g_wh1h); cudaGetSymbolAddress((void**)&wh1l, g_wh1l);
    cudaGetSymbolAddress((void**)&wx2h, g_wx2h); cudaGetSymbolAddress((void**)&wx2l, g_wx2l);
    cudaGetSymbolAddress((void**)&wh2h, g_wh2h); cudaGetSymbolAddress((void**)&wh2l, g_wh2l);
    cudaGetSymbolAddress((void**)&wx3h, g_wx3h); cudaGetSymbolAddress((void**)&wx3l, g_wx3l);
    cudaGetSymbolAddress((void**)&wh3h, g_wh3h); cudaGetSymbolAddress((void**)&wh3l, g_wh3l);

    const int Mall = BDIM * TDIM * LDIM;   // 131072
    const int Mst  = BDIM * LDIM;          // 4096
    const int SMEM_MMA = 2 * BUFSZ;        // 81920 (also covers 128*132*4 staging)
    cudaFuncSetAttribute(mma_gemm_conv, cudaFuncAttributeMaxDynamicSharedMemorySize, SMEM_MMA);
    dim3 blk(256);

    // ---- weight/bias conversions (gate-interleaved) ----
    wconv_kernel<<<(256*192  + 255)/256, 256>>>(Wh1, wh1h, wh1l, 192, 256);
    wconv_kernel<<<(512*192  + 255)/256, 256>>>(Wx2, wx2h, wx2l, 192, 512);
    wconv_kernel<<<(512*384  + 255)/256, 256>>>(Wh2, wh2h, wh2l, 384, 512);
    wconv_kernel<<<(1024*384 + 255)/256, 256>>>(Wx3, wx3h, wx3l, 384, 1024);
    wconv_kernel<<<(1024*768 + 255)/256, 256>>>(Wh3, wh3h, wh3l, 768, 1024);
    permute_bias<<<1, 256>>>(b1, pb1, 256);
    permute_bias<<<2, 256>>>(b2, pb2, 512);
    permute_bias<<<4, 256>>>(b3, pb3, 1024);
    permute_wx1<<<3, 256>>>(Wx1, wx1p);

    // ================= Layer 1 =================
    gemm_conv_kernel<<<dim3(2, Mall / BM), blk>>>(x, wx1p, pb1, xg1, Mall, 256, 3, 0);
    gate0_kernel<<<(Mst * 64 + 255) / 256, 256>>>(
        (const float4*)xg1, cst, h1, hhi, hlo, Mst * 64);
    for (int t = 1; t < TDIM; t++) {
        mma_gemm_conv<<<dim3(2, Mst / 128), blk, SMEM_MMA>>>(
            hhi, hlo, wh1h, wh1l, nullptr, nullptr,
            xg1 + (size_t)t * Mst * 256, cst, h1 + (size_t)t * Mst * 64, hhi, hlo,
            Mst, 256, 192, 6, 1);
    }
    {
        size_t tot = (size_t)TDIM * Mst * 64;
        bn_convert<<<(int)((tot + 255) / 256), 256>>>(h1, g1, be1, m1, v1, bn1h, bn1l, tot, 6);
    }

    // ================= Layer 2 =================
    mma_gemm_conv<<<dim3(4, Mall / 128), blk, SMEM_MMA>>>(
        bn1h, bn1l, wx2h, wx2l, pb2, xg2,
        nullptr, nullptr, nullptr, nullptr, nullptr,
        Mall, 512, 192, 6, 0);
    gate0_kernel<<<(Mst * 128 + 255) / 256, 256>>>(
        (const float4*)xg2, cst, h2, hhi, hlo, Mst * 128);
    for (int t = 1; t < TDIM; t++) {
        mma_gemm_conv<<<dim3(4, Mst / 128), blk, SMEM_MMA>>>(
            hhi, hlo, wh2h, wh2l, nullptr, nullptr,
            xg2 + (size_t)t * Mst * 512, cst, h2 + (size_t)t * Mst * 128, hhi, hlo,
            Mst, 512, 384, 7, 1);
    }
    {
        size_t tot = (size_t)TDIM * Mst * 128;
        bn_convert<<<(int)((tot + 255) / 256), 256>>>(h2, g2, be2, m2, v2, bn2h, bn2l, tot, 7);
    }

    // ================= Layer 3 =================
    mma_gemm_conv<<<dim3(8, Mall / 128), blk, SMEM_MMA>>>(
        bn2h, bn2l, wx3h, wx3l, pb3, xg3,
        nullptr, nullptr, nullptr, nullptr, nullptr,
        Mall, 1024, 384, 7, 0);
    gate0_kernel<<<(Mst * 256 + 255) / 256, 256>>>(
        (const float4*)xg3, cst, hst, hhi, hlo, Mst * 256);
    for (int t = 1; t < TDIM; t++) {
        mma_gemm_conv<<<dim3(8, Mst / 128), blk, SMEM_MMA>>>(
            hhi, hlo, wh3h, wh3l, nullptr, nullptr,
            xg3 + (size_t)t * Mst * 1024, cst, hst, hhi, hlo,
            Mst, 1024, 768, 8, 1);
    }
    {
        size_t tot = (size_t)Mst * 256;
        bn_kernel<<<(int)((tot + 255) / 256), 256>>>(hst, g3, be3, m3, v3, tot, 8);
    }

    // ================= Dense head =================
    fc_kernel<<<dim3(1024 / 64, 8), blk>>>(hst, D1, prt, 1024, 32768, 4096);
    fc_reduce_relu<<<(32 * 1024 + 255) / 256, 256>>>(prt, db1, a1, 1024, 8);
    fc_kernel<<<dim3(512 / 64, 2), blk>>>(a1, D2, prt, 512, 1024, 512);
    fc_reduce_relu<<<(32 * 512 + 255) / 256, 256>>>(prt, db2, a2, 512, 2);
    fc3_softmax<<<1, 256>>>(a2, D3, db3, out);
}

// round 15
// speedup vs baseline: 1.2231x; 1.1102x over previous
#include <cuda_runtime.h>
#include <cuda_bf16.h>
#include <math.h>
#include <cstdint>

#define BDIM 32
#define TDIM 32
#define LDIM 128
#define LOG_L 7

// ================= scratch (static device globals) =================
__device__ float g_xg1[(size_t)TDIM*BDIM*LDIM*256];   // [T][B][L][4F1] (gate-interleaved)
__device__ float g_xg2[(size_t)TDIM*BDIM*LDIM*512];   // [T][B][L][4F2]
__device__ float g_xg3[(size_t)TDIM*BDIM*LDIM*1024];  // [T][B][L][4F3]
__device__ float g_h1 [(size_t)TDIM*BDIM*LDIM*64];    // [T][B][L][F1]
__device__ float g_h2 [(size_t)TDIM*BDIM*LDIM*128];   // [T][B][L][F2]
__device__ float g_hst[(size_t)BDIM*LDIM*256];
__device__ float g_cst[(size_t)BDIM*LDIM*256];
__device__ float g_prt[(size_t)8*BDIM*1024];
__device__ float g_a1 [(size_t)BDIM*1024];
__device__ float g_a2 [(size_t)BDIM*512];
__device__ float g_pb1[256], g_pb2[512], g_pb3[1024];
__device__ float g_wx1p[3*256];

// bf16 hi/lo activations — 2 ping-pong buffers each
__device__ __nv_bfloat16 g_hhi[(size_t)2*BDIM*LDIM*256];
__device__ __nv_bfloat16 g_hlo[(size_t)2*BDIM*LDIM*256];
__device__ __nv_bfloat16 g_bn1h[(size_t)TDIM*BDIM*LDIM*64];
__device__ __nv_bfloat16 g_bn1l[(size_t)TDIM*BDIM*LDIM*64];
__device__ __nv_bfloat16 g_bn2h[(size_t)TDIM*BDIM*LDIM*128];
__device__ __nv_bfloat16 g_bn2l[(size_t)TDIM*BDIM*LDIM*128];

// bf16 hi/lo weights, [N,K] layout, N gate-interleaved (n' = 4f+g)
__device__ __nv_bfloat16 g_wh1h[256*192],  g_wh1l[256*192];
__device__ __nv_bfloat16 g_wx2h[512*192],  g_wx2l[512*192];
__device__ __nv_bfloat16 g_wh2h[512*384],  g_wh2l[512*384];
__device__ __nv_bfloat16 g_wx3h[1024*384], g_wx3l[1024*384];
__device__ __nv_bfloat16 g_wh3h[1024*768], g_wh3l[1024*768];

// ================= helpers =================
__device__ __forceinline__ uint32_t smem_to_u32(const void* p) {
    uint32_t a;
    asm("{ .reg .u64 t; cvta.to.shared.u64 t, %1; cvt.u32.u64 %0, t; }" : "=r"(a) : "l"(p));
    return a;
}
__device__ __forceinline__ void cp_async16(uint32_t saddr, const void* gaddr, uint32_t sz) {
    asm volatile("cp.async.cg.shared.global [%0], [%1], 16, %2;"
                 :: "r"(saddr), "l"(gaddr), "r"(sz));
}
#define CP_COMMIT() asm volatile("cp.async.commit_group;" ::: "memory")
#define CP_WAIT(n)  asm volatile("cp.async.wait_group %0;" :: "n"(n) : "memory")
#define LDSM_X4(r, addr) \
    asm volatile("ldmatrix.sync.aligned.m8n8.x4.shared.b16 {%0,%1,%2,%3}, [%4];" \
        : "=r"((r)[0]), "=r"((r)[1]), "=r"((r)[2]), "=r"((r)[3]) : "r"(addr))

__device__ __forceinline__ void mma16816(float* c, const uint32_t* a,
                                         uint32_t b0, uint32_t b1) {
    asm volatile("mma.sync.aligned.m16n8k16.row.col.f32.bf16.bf16.f32 "
        "{%0,%1,%2,%3}, {%4,%5,%6,%7}, {%8,%9}, {%0,%1,%2,%3};"
        : "+f"(c[0]), "+f"(c[1]), "+f"(c[2]), "+f"(c[3])
        : "r"(a[0]), "r"(a[1]), "r"(a[2]), "r"(a[3]), "r"(b0), "r"(b1));
}
__device__ __forceinline__ float hsig(float x) {
    return fminf(fmaxf(0.2f * x + 0.5f, 0.f), 1.f);
}

#define SROW  80
#define TILE  (128*SROW)   // 10240
#define BUFSZ (4*TILE)
#define STROW 132          // fp32 staging row stride (floats)

// --- shared mainloop body (macro to guarantee identical codegen in both kernels) ---
#define MMA_MAINLOOP_BODY \
    const uint32_t sb = smem_to_u32(smem); \
    const int tid  = threadIdx.x; \
    const int wid  = tid >> 5; \
    const int lane = tid & 31; \
    const int wm   = wid >> 1; \
    const int wn   = wid & 1; \
    const int m0   = blockIdx.y * 128; \
    const int n0   = blockIdx.x * 128; \
    const int Cin  = 1 << logCin; \
    const int nk   = K >> 5; \
    float acc[2][8][4]; \
    _Pragma("unroll") \
    for (int mt = 0; mt < 2; mt++) \
        _Pragma("unroll") \
        for (int nt = 0; nt < 8; nt++) \
            _Pragma("unroll") \
            for (int r = 0; r < 4; r++) acc[mt][nt][r] = 0.f; \
    auto load_chunk = [&](int c, int buf) { \
        const int k0  = c << 5; \
        const int ks  = k0 >> logCin; \
        const int ci0 = k0 & (Cin - 1); \
        const uint32_t sbuf = sb + buf * BUFSZ; \
        _Pragma("unroll") \
        for (int i = 0; i < 2; i++) { \
            int idx = tid + (i << 8); \
            int row = idx >> 2; \
            int seg = idx & 3; \
            int m  = m0 + row; \
            int l  = m & (LDIM - 1); \
            int ll = l + ks - 1; \
            uint32_t sz = (ll >= 0 && ll < LDIM) ? 16u : 0u; \
            int llc = ll < 0 ? 0 : (ll > LDIM - 1 ? LDIM - 1 : ll); \
            size_t aoff = (size_t)(m - l + llc) * Cin + ci0 + seg * 8; \
            uint32_t sa = sbuf + row * SROW + seg * 16; \
            cp_async16(sa,            Ahi + aoff, sz); \
            cp_async16(sa + TILE,     Alo + aoff, sz); \
            size_t boff = (size_t)(n0 + row) * K + k0 + seg * 8; \
            cp_async16(sa + 2 * TILE, Bhi + boff, 16u); \
            cp_async16(sa + 3 * TILE, Blo + boff, 16u); \
        } \
    }; \
    const int a_row = lane & 15; \
    const int a_k16 = (lane & 16) ? 16 : 0; \
    const int b_row = (lane & 7) + ((lane & 16) ? 8 : 0); \
    const int b_k16 = (lane & 8) ? 16 : 0; \
    load_chunk(0, 0); \
    CP_COMMIT(); \
    for (int c = 0; c < nk; c++) { \
        if (c + 1 < nk) { \
            load_chunk(c + 1, (c + 1) & 1); \
            CP_COMMIT(); \
            CP_WAIT(1); \
        } else { \
            CP_WAIT(0); \
        } \
        __syncthreads(); \
        const uint32_t sbuf = sb + (c & 1) * BUFSZ; \
        _Pragma("unroll") \
        for (int ks = 0; ks < 2; ks++) { \
            uint32_t ah[2][4], al[2][4]; \
            _Pragma("unroll") \
            for (int mt = 0; mt < 2; mt++) { \
                uint32_t ad = sbuf + (wm * 32 + mt * 16 + a_row) * SROW \
                                   + ks * 32 + a_k16; \
                LDSM_X4(ah[mt], ad); \
                LDSM_X4(al[mt], ad + TILE); \
            } \
            _Pragma("unroll") \
            for (int n2 = 0; n2 < 4; n2++) { \
                uint32_t bd = sbuf + 2 * TILE \
                            + (wn * 64 + n2 * 16 + b_row) * SROW \
                            + ks * 32 + b_k16; \
                uint32_t bh[4], bl[4]; \
                LDSM_X4(bh, bd); \
                LDSM_X4(bl, bd + TILE); \
                _Pragma("unroll") \
                for (int mt = 0; mt < 2; mt++) { \
                    mma16816(acc[mt][n2 * 2],     ah[mt], bh[0], bh[1]); \
                    mma16816(acc[mt][n2 * 2],     ah[mt], bl[0], bl[1]); \
                    mma16816(acc[mt][n2 * 2],     al[mt], bh[0], bh[1]); \
                    mma16816(acc[mt][n2 * 2 + 1], ah[mt], bh[2], bh[3]); \
                    mma16816(acc[mt][n2 * 2 + 1], ah[mt], bl[2], bl[3]); \
                    mma16816(acc[mt][n2 * 2 + 1], al[mt], bh[2], bh[3]); \
                } \
            } \
        } \
        __syncthreads(); \
    }

// ================= input-conv GEMM: +bias, store C =================
__global__ __launch_bounds__(256, 2) void mma_gemm_bias(
    const __nv_bfloat16* __restrict__ Ahi, const __nv_bfloat16* __restrict__ Alo,
    const __nv_bfloat16* __restrict__ Bhi, const __nv_bfloat16* __restrict__ Blo,
    const float* __restrict__ bias, float* __restrict__ C,
    int M, int N, int K, int logCin)
{
    extern __shared__ char smem[];
    MMA_MAINLOOP_BODY

    const int r0 = lane >> 2;
    const int q  = lane & 3;
    const int cp = q * 2;
    #pragma unroll
    for (int mt = 0; mt < 2; mt++) {
        #pragma unroll
        for (int nt = 0; nt < 8; nt++) {
            int row = m0 + wm * 32 + mt * 16 + r0;
            int col = n0 + wn * 64 + nt * 8 + cp;
            float bx = bias[col], by = bias[col + 1];
            float2 v0 = make_float2(acc[mt][nt][0] + bx, acc[mt][nt][1] + by);
            float2 v1 = make_float2(acc[mt][nt][2] + bx, acc[mt][nt][3] + by);
            *reinterpret_cast<float2*>(C + (size_t)row * N + col)       = v0;
            *reinterpret_cast<float2*>(C + (size_t)(row + 8) * N + col) = v1;
        }
    }
}

// ================= recurrent GEMM + fused LSTM gate =================
// Reads prev-step h (Ahi/Alo), writes NEW buffers (hhoDst/hloDst) — no WAR race.
__global__ __launch_bounds__(256, 2) void mma_gemm_gate(
    const __nv_bfloat16* __restrict__ Ahi, const __nv_bfloat16* __restrict__ Alo,
    const __nv_bfloat16* __restrict__ Bhi, const __nv_bfloat16* __restrict__ Blo,
    const float* __restrict__ xg, float* __restrict__ cst,
    float* __restrict__ hseq,
    __nv_bfloat16* __restrict__ hhiDst, __nv_bfloat16* __restrict__ hloDst,
    int M, int N, int K, int logCin)
{
    extern __shared__ char smem[];
    MMA_MAINLOOP_BODY

    const int r0 = lane >> 2;
    const int q  = lane & 3;
    // ---- stage accumulators into SMEM (fp32, row stride STROW) ----
    float* st = reinterpret_cast<float*>(smem);
    #pragma unroll
    for (int mt = 0; mt < 2; mt++) {
        #pragma unroll
        for (int nt = 0; nt < 8; nt++) {
            int row_l = wm * 32 + mt * 16 + r0;
            int col_l = wn * 64 + nt * 8 + q * 2;
            *reinterpret_cast<float2*>(&st[row_l * STROW + col_l]) =
                make_float2(acc[mt][nt][0], acc[mt][nt][1]);
            *reinterpret_cast<float2*>(&st[(row_l + 8) * STROW + col_l]) =
                make_float2(acc[mt][nt][2], acc[mt][nt][3]);
        }
    }
    __syncthreads();
    // ---- coalesced gate pass: warp = row, lanes sweep 32 features ----
    const int F = N >> 2;
    const int f0 = n0 >> 2;
    #pragma unroll
    for (int i = 0; i < 16; i++) {
        int e   = tid + (i << 8);
        int row = e >> 5;
        int f   = e & 31;
        float4 g4 = *reinterpret_cast<const float4*>(&st[row * STROW + 4 * f]);
        int m = m0 + row;
        float4 x4 = *reinterpret_cast<const float4*>(xg + (size_t)m * N + n0 + 4 * f);
        float iv = g4.x + x4.x;
        float fv = g4.y + x4.y;
        float cv = g4.z + x4.z;
        float ov = g4.w + x4.w;
        size_t sidx = (size_t)m * F + f0 + f;
        float cn = hsig(fv) * cst[sidx] + hsig(iv) * fmaxf(cv, 0.f);
        cst[sidx] = cn;
        float hn = hsig(ov) * fmaxf(cn, 0.f);
        hseq[sidx] = hn;
        __nv_bfloat16 hi = __float2bfloat16(hn);
        hhiDst[sidx] = hi;
        hloDst[sidx] = __float2bfloat16(hn - __bfloat162float(hi));
    }
}

// ===== t=0 gate (h=c=0): c = hsig(i)*relu(cg); also initializes cst/h buffers =====
__global__ void gate0_kernel(const float4* __restrict__ xg, float* __restrict__ cst,
                             float* __restrict__ hseq,
                             __nv_bfloat16* __restrict__ hhi,
                             __nv_bfloat16* __restrict__ hlo, int total)
{
    int idx = blockIdx.x * blockDim.x + threadIdx.x;
    if (idx >= total) return;
    float4 x4 = xg[idx];
    float cn = hsig(x4.x) * fmaxf(x4.z, 0.f);
    cst[idx] = cn;
    float hn = hsig(x4.w) * fmaxf(cn, 0.f);
    hseq[idx] = hn;
    __nv_bfloat16 hi = __float2bfloat16(hn);
    hhi[idx] = hi;
    hlo[idx] = __float2bfloat16(hn - __bfloat162float(hi));
}

// ===== weight convert: W[K,N] fp32 -> [N',K] bf16 hi/lo with gate interleave =====
__global__ void wconv_kernel(const float* __restrict__ W,
                             __nv_bfloat16* __restrict__ Bh, __nv_bfloat16* __restrict__ Bl,
                             int K, int N)
{
    int idx = blockIdx.x * blockDim.x + threadIdx.x;
    if (idx >= N * K) return;
    int np = idx / K, k = idx - np * K;
    int F = N >> 2;
    int n = (np & 3) * F + (np >> 2);
    float x = W[(size_t)k * N + n];
    __nv_bfloat16 hi = __float2bfloat16(x);
    Bh[idx] = hi;
    Bl[idx] = __float2bfloat16(x - __bfloat162float(hi));
}

// ===== bias permute: pb[4f+g] = b[g*F+f] =====
__global__ void permute_bias(const float* __restrict__ b, float* __restrict__ pb, int N)
{
    int idx = blockIdx.x * blockDim.x + threadIdx.x;
    if (idx >= N) return;
    int F = N >> 2;
    pb[idx] = b[(idx & 3) * F + (idx >> 2)];
}

// ===== permute Wx1 [3,256] fp32 -> gate-interleaved cols =====
__global__ void permute_wx1(const float* __restrict__ W, float* __restrict__ Wp)
{
    int idx = blockIdx.x * blockDim.x + threadIdx.x;
    if (idx >= 3 * 256) return;
    int k = idx >> 8, np = idx & 255;
    Wp[idx] = W[k * 256 + (np & 3) * 64 + (np >> 2)];
}

// ================= fp32 implicit GEMM (layer-1 input, K=3), T-major output ========
#define BM 128
#define BN 128
#define BK 8
__global__ __launch_bounds__(256) void gemm_conv_kernel(
    const float* __restrict__ A, const float* __restrict__ W,
    const float* __restrict__ bias, float* __restrict__ C,
    int M, int N, int K, int logCin)
{
    __shared__ float As[BK][BM];
    __shared__ float Bs[BK][BN];
    int tid = threadIdx.x;
    int m0 = blockIdx.y * BM;
    int n0 = blockIdx.x * BN;
    int tx = tid & 15, ty = tid >> 4;
    int a_row = tid >> 1;
    int a_col = (tid & 1) * 4;
    int b_k = tid >> 5;
    int b_n = (tid & 31) * 4;
    int Cin = 1 << logCin;
    float acc[8][8];
    #pragma unroll
    for (int i = 0; i < 8; i++)
        #pragma unroll
        for (int j = 0; j < 8; j++) acc[i][j] = 0.f;
    for (int k0 = 0; k0 < K; k0 += BK) {
        int m = m0 + a_row;
        #pragma unroll
        for (int i = 0; i < 4; i++) {
            int kk = k0 + a_col + i;
            float v = 0.f;
            if (m < M && kk < K) {
                int l = m & (LDIM - 1);
                int ks = kk >> logCin;
                int ci = kk - (ks << logCin);
                int ll = l + ks - 1;
                if (ll >= 0 && ll < LDIM)
                    v = A[(size_t)(m - l + ll) * Cin + ci];
            }
            As[a_col + i][a_row] = v;
        }
        {
            int kk = k0 + b_k;
            float4 v = make_float4(0.f, 0.f, 0.f, 0.f);
            if (kk < K && n0 + b_n + 3 < N)
                v = *reinterpret_cast<const float4*>(&W[(size_t)kk * N + n0 + b_n]);
            Bs[b_k][b_n] = v.x; Bs[b_k][b_n+1] = v.y; Bs[b_k][b_n+2] = v.z; Bs[b_k][b_n+3] = v.w;
        }
        __syncthreads();
        #pragma unroll
        for (int kk = 0; kk < BK; kk++) {
            float af[8], bf[8];
            #pragma unroll
            for (int i = 0; i < 8; i++) af[i] = As[kk][ty * 8 + i];
            #pragma unroll
            for (int j = 0; j < 8; j++) bf[j] = Bs[kk][tx * 8 + j];
            #pragma unroll
            for (int i = 0; i < 8; i++)
                #pragma unroll
                for (int j = 0; j < 8; j++) acc[i][j] += af[i] * bf[j];
        }
        __syncthreads();
    }
    #pragma unroll
    for (int i = 0; i < 8; i++) {
        int m = m0 + ty * 8 + i;
        if (m >= M) continue;
        int l = m & (LDIM - 1);
        int bt = m >> LOG_L;
        int b = bt >> 5;
        int t = bt & 31;
        int mp = ((t << 5) + b) * LDIM + l;
        #pragma unroll
        for (int j = 0; j < 8; j++) {
            int n = n0 + tx * 8 + j;
            if (n >= N) continue;
            float v = acc[i][j];
            if (bias) v += bias[n];
            C[(size_t)mp * N + n] = v;
        }
    }
}

// ================= BN (fp32 in place) =================
__global__ void bn_kernel(float* __restrict__ x, const float* __restrict__ gw,
                          const float* __restrict__ be, const float* __restrict__ mu,
                          const float* __restrict__ var, size_t total, int logC)
{
    size_t idx = (size_t)blockIdx.x * blockDim.x + threadIdx.x;
    if (idx >= total) return;
    int C = 1 << logC;
    int ch = (int)(idx & (size_t)(C - 1));
    x[idx] = (x[idx] - mu[ch]) * rsqrtf(var[ch] + 1e-3f) * gw[ch] + be[ch];
}

// ================= BN -> bf16 hi/lo convert =================
__global__ void bn_convert(const float* __restrict__ x, const float* __restrict__ gw,
                           const float* __restrict__ be, const float* __restrict__ mu,
                           const float* __restrict__ var,
                           __nv_bfloat16* __restrict__ oh, __nv_bfloat16* __restrict__ ol,
                           size_t total, int logC)
{
    size_t idx = (size_t)blockIdx.x * blockDim.x + threadIdx.x;
    if (idx >= total) return;
    int C = 1 << logC;
    int ch = (int)(idx & (size_t)(C - 1));
    float v = (x[idx] - mu[ch]) * rsqrtf(var[ch] + 1e-3f) * gw[ch] + be[ch];
    __nv_bfloat16 hi = __float2bfloat16(v);
    oh[idx] = hi;
    ol[idx] = __float2bfloat16(v - __bfloat162float(hi));
}

// ================= dense head (fp32, small) =================
__global__ __launch_bounds__(256) void fc_kernel(
    const float* __restrict__ A, const float* __restrict__ W,
    float* __restrict__ partial, int N, int K, int kchunk)
{
    __shared__ float As[32][33];
    int tid = threadIdx.x;
    int n0 = blockIdx.x * 64;
    int col = tid & 63;
    int rq = tid >> 6;
    int k0 = blockIdx.y * kchunk;
    int kend = min(K, k0 + kchunk);
    float acc[8];
    #pragma unroll
    for (int r = 0; r < 8; r++) acc[r] = 0.f;
    int a_m = tid >> 3;
    int a_k = (tid & 7) * 4;
    for (int kb = k0; kb < kend; kb += 32) {
        #pragma unroll
        for (int i = 0; i < 4; i++) {
            int kk = kb + a_k + i;
            As[a_m][a_k + i] = (kk < K) ? A[(size_t)a_m * K + kk] : 0.f;
        }
        __syncthreads();
        #pragma unroll
        for (int kk = 0; kk < 32; kk++) {
            float w = W[(size_t)(kb + kk) * N + n0 + col];
            #pragma unroll
            for (int r = 0; r < 8; r++) acc[r] += As[rq * 8 + r][kk] * w;
        }
        __syncthreads();
    }
    #pragma unroll
    for (int r = 0; r < 8; r++) {
        int m = rq * 8 + r;
        partial[((size_t)blockIdx.y * 32 + m) * N + n0 + col] = acc[r];
    }
}

__global__ void fc_reduce_relu(const float* __restrict__ partial,
                               const float* __restrict__ bias,
                               float* __restrict__ out, int N, int KS)
{
    int idx = blockIdx.x * blockDim.x + threadIdx.x;
    if (idx >= 32 * N) return;
    int m = idx / N, n = idx - m * N;
    float s = bias[n];
    for (int ks = 0; ks < KS; ks++)
        s += partial[((size_t)ks * 32 + m) * N + n];
    out[idx] = fmaxf(s, 0.f);
}

__global__ void fc3_softmax(const float* __restrict__ A, const float* __restrict__ W,
                            const float* __restrict__ bias, float* __restrict__ out)
{
    __shared__ float logits[32][5];
    int tid = threadIdx.x;
    int bm = tid >> 3, j = tid & 7;
    if (bm < 32 && j < 5) {
        float s = bias[j];
        for (int k = 0; k < 512; k++)
            s += A[bm * 512 + k] * W[k * 5 + j];
        logits[bm][j] = s;
    }
    __syncthreads();
    if (bm < 32 && j == 0) {
        float mx = logits[bm][0];
        for (int q = 1; q < 5; q++) mx = fmaxf(mx, logits[bm][q]);
        float e[5], sum = 0.f;
        for (int q = 0; q < 5; q++) { e[q] = expf(logits[bm][q] - mx); sum += e[q]; }
        for (int q = 0; q < 5; q++) out[bm * 5 + q] = e[q] / sum;
    }
}

// ================= host orchestration =================
extern "C" void kernel_launch(void* const* d_in, const int* in_sizes, int n_in,
                              void* d_out, int out_size)
{
    const float* x   = (const float*)d_in[0];
    const float* Wx1 = (const float*)d_in[1];
    const float* Wh1 = (const float*)d_in[2];
    const float* b1  = (const float*)d_in[3];
    const float* Wx2 = (const float*)d_in[4];
    const float* Wh2 = (const float*)d_in[5];
    const float* b2  = (const float*)d_in[6];
    const float* Wx3 = (const float*)d_in[7];
    const float* Wh3 = (const float*)d_in[8];
    const float* b3  = (const float*)d_in[9];
    const float* g1  = (const float*)d_in[10];
    const float* be1 = (const float*)d_in[11];
    const float* m1  = (const float*)d_in[12];
    const float* v1  = (const float*)d_in[13];
    const float* g2  = (const float*)d_in[14];
    const float* be2 = (const float*)d_in[15];
    const float* m2  = (const float*)d_in[16];
    const float* v2  = (const float*)d_in[17];
    const float* g3  = (const float*)d_in[18];
    const float* be3 = (const float*)d_in[19];
    const float* m3  = (const float*)d_in[20];
    const float* v3  = (const float*)d_in[21];
    const float* D1  = (const float*)d_in[22];
    const float* db1 = (const float*)d_in[23];
    const float* D2  = (const float*)d_in[24];
    const float* db2 = (const float*)d_in[25];
    const float* D3  = (const float*)d_in[26];
    const float* db3 = (const float*)d_in[27];
    float* out = (float*)d_out;

    float *xg1, *xg2, *xg3, *h1, *h2, *hst, *cst, *prt, *a1, *a2;
    float *pb1, *pb2, *pb3, *wx1p;
    __nv_bfloat16 *hhi, *hlo, *bn1h, *bn1l, *bn2h, *bn2l;
    __nv_bfloat16 *wh1h, *wh1l, *wx2h, *wx2l, *wh2h, *wh2l, *wx3h, *wx3l, *wh3h, *wh3l;
    cudaGetSymbolAddress((void**)&xg1, g_xg1);
    cudaGetSymbolAddress((void**)&xg2, g_xg2);
    cudaGetSymbolAddress((void**)&xg3, g_xg3);
    cudaGetSymbolAddress((void**)&h1,  g_h1);
    cudaGetSymbolAddress((void**)&h2,  g_h2);
    cudaGetSymbolAddress((void**)&hst, g_hst);
    cudaGetSymbolAddress((void**)&cst, g_cst);
    cudaGetSymbolAddress((void**)&prt, g_prt);
    cudaGetSymbolAddress((void**)&a1,  g_a1);
    cudaGetSymbolAddress((void**)&a2,  g_a2);
    cudaGetSymbolAddress((void**)&pb1, g_pb1);
    cudaGetSymbolAddress((void**)&pb2, g_pb2);
    cudaGetSymbolAddress((void**)&pb3, g_pb3);
    cudaGetSymbolAddress((void**)&wx1p, g_wx1p);
    cudaGetSymbolAddress((void**)&hhi, g_hhi);
    cudaGetSymbolAddress((void**)&hlo, g_hlo);
    cudaGetSymbolAddress((void**)&bn1h, g_bn1h);
    cudaGetSymbolAddress((void**)&bn1l, g_bn1l);
    cudaGetSymbolAddress((void**)&bn2h, g_bn2h);
    cudaGetSymbolAddress((void**)&bn2l, g_bn2l);
    cudaGetSymbolAddress((void**)&wh1h, g_wh1h); cudaGetSymbolAddress((void**)&wh1l, g_wh1l);
    cudaGetSymbolAddress((void**)&wx2h, g_wx2h); cudaGetSymbolAddress((void**)&wx2l, g_wx2l);
    cudaGetSymbolAddress((void**)&wh2h, g_wh2h); cudaGetSymbolAddress((void**)&wh2l, g_wh2l);
    cudaGetSymbolAddress((void**)&wx3h, g_wx3h); cudaGetSymbolAddress((void**)&wx3l, g_wx3l);
    cudaGetSymbolAddress((void**)&wh3h, g_wh3h); cudaGetSymbolAddress((void**)&wh3l, g_wh3l);

    const int Mall = BDIM * TDIM * LDIM;   // 131072
    const int Mst  = BDIM * LDIM;          // 4096
    const size_t HBUF = (size_t)BDIM * LDIM * 256;   // ping-pong stride (elems)
    const int SMEM_MMA = 2 * BUFSZ;        // 81920 (also covers 128*132*4 staging)
    cudaFuncSetAttribute(mma_gemm_bias, cudaFuncAttributeMaxDynamicSharedMemorySize, SMEM_MMA);
    cudaFuncSetAttribute(mma_gemm_gate, cudaFuncAttributeMaxDynamicSharedMemorySize, SMEM_MMA);
    dim3 blk(256);

    // ---- weight/bias conversions (gate-interleaved) ----
    wconv_kernel<<<(256*192  + 255)/256, 256>>>(Wh1, wh1h, wh1l, 192, 256);
    wconv_kernel<<<(512*192  + 255)/256, 256>>>(Wx2, wx2h, wx2l, 192, 512);
    wconv_kernel<<<(512*384  + 255)/256, 256>>>(Wh2, wh2h, wh2l, 384, 512);
    wconv_kernel<<<(1024*384 + 255)/256, 256>>>(Wx3, wx3h, wx3l, 384, 1024);
    wconv_kernel<<<(1024*768 + 255)/256, 256>>>(Wh3, wh3h, wh3l, 768, 1024);
    permute_bias<<<1, 256>>>(b1, pb1, 256);
    permute_bias<<<2, 256>>>(b2, pb2, 512);
    permute_bias<<<4, 256>>>(b3, pb3, 1024);
    permute_wx1<<<3, 256>>>(Wx1, wx1p);

    // ================= Layer 1 =================
    gemm_conv_kernel<<<dim3(2, Mall / BM), blk>>>(x, wx1p, pb1, xg1, Mall, 256, 3, 0);
    gate0_kernel<<<(Mst * 64 + 255) / 256, 256>>>(
        (const float4*)xg1, cst, h1, hhi, hlo, Mst * 64);
    for (int t = 1; t < TDIM; t++) {
        int pi = (t - 1) & 1, po = t & 1;
        mma_gemm_gate<<<dim3(2, Mst / 128), blk, SMEM_MMA>>>(
            hhi + pi * HBUF, hlo + pi * HBUF, wh1h, wh1l,
            xg1 + (size_t)t * Mst * 256, cst, h1 + (size_t)t * Mst * 64,
            hhi + po * HBUF, hlo + po * HBUF,
            Mst, 256, 192, 6);
    }
    {
        size_t tot = (size_t)TDIM * Mst * 64;
        bn_convert<<<(int)((tot + 255) / 256), 256>>>(h1, g1, be1, m1, v1, bn1h, bn1l, tot, 6);
    }

    // ================= Layer 2 =================
    mma_gemm_bias<<<dim3(4, Mall / 128), blk, SMEM_MMA>>>(
        bn1h, bn1l, wx2h, wx2l, pb2, xg2, Mall, 512, 192, 6);
    gate0_kernel<<<(Mst * 128 + 255) / 256, 256>>>(
        (const float4*)xg2, cst, h2, hhi, hlo, Mst * 128);
    for (int t = 1; t < TDIM; t++) {
        int pi = (t - 1) & 1, po = t & 1;
        mma_gemm_gate<<<dim3(4, Mst / 128), blk, SMEM_MMA>>>(
            hhi + pi * HBUF, hlo + pi * HBUF, wh2h, wh2l,
            xg2 + (size_t)t * Mst * 512, cst, h2 + (size_t)t * Mst * 128,
            hhi + po * HBUF, hlo + po * HBUF,
            Mst, 512, 384, 7);
    }
    {
        size_t tot = (size_t)TDIM * Mst * 128;
        bn_convert<<<(int)((tot + 255) / 256), 256>>>(h2, g2, be2, m2, v2, bn2h, bn2l, tot, 7);
    }

    // ================= Layer 3 =================
    mma_gemm_bias<<<dim3(8, Mall / 128), blk, SMEM_MMA>>>(
        bn2h, bn2l, wx3h, wx3l, pb3, xg3, Mall, 1024, 384, 7);
    gate0_kernel<<<(Mst * 256 + 255) / 256, 256>>>(
        (const float4*)xg3, cst, hst, hhi, hlo, Mst * 256);
    for (int t = 1; t < TDIM; t++) {
        int pi = (t - 1) & 1, po = t & 1;
        mma_gemm_gate<<<dim3(8, Mst / 128), blk, SMEM_MMA>>>(
            hhi + pi * HBUF, hlo + pi * HBUF, wh3h, wh3l,
            xg3 + (size_t)t * Mst * 1024, cst, hst,
            hhi + po * HBUF, hlo + po * HBUF,
            Mst, 1024, 768, 8);
    }
    {
        size_t tot = (size_t)Mst * 256;
        bn_kernel<<<(int)((tot + 255) / 256), 256>>>(hst, g3, be3, m3, v3, tot, 8);
    }

    // ================= Dense head =================
    fc_kernel<<<dim3(1024 / 64, 8), blk>>>(hst, D1, prt, 1024, 32768, 4096);
    fc_reduce_relu<<<(32 * 1024 + 255) / 256, 256>>>(prt, db1, a1, 1024, 8);
    fc_kernel<<<dim3(512 / 64, 2), blk>>>(a1, D2, prt, 512, 1024, 512);
    fc_reduce_relu<<<(32 * 512 + 255) / 256, 256>>>(prt, db2, a2, 512, 2);
    fc3_softmax<<<1, 256>>>(a2, D3, db3, out);
}

// round 16
// speedup vs baseline: 1.4936x; 1.2212x over previous
#include <cuda_runtime.h>
#include <cuda_fp16.h>
#include <math.h>
#include <cstdint>

#define BDIM 32
#define TDIM 32
#define LDIM 128
#define LOG_L 7

// ================= scratch (static device globals) =================
__device__ float g_xg1[(size_t)TDIM*BDIM*LDIM*256];   // [T][B][L][4F1] (gate-interleaved)
__device__ float g_xg2[(size_t)TDIM*BDIM*LDIM*512];   // [T][B][L][4F2]
__device__ float g_xg3[(size_t)TDIM*BDIM*LDIM*1024];  // [T][B][L][4F3]
__device__ float g_h1 [(size_t)TDIM*BDIM*LDIM*64];    // [T][B][L][F1]
__device__ float g_h2 [(size_t)TDIM*BDIM*LDIM*128];   // [T][B][L][F2]
__device__ float g_hst[(size_t)BDIM*LDIM*256];
__device__ float g_cst[(size_t)BDIM*LDIM*256];
__device__ float g_prt[(size_t)8*BDIM*1024];
__device__ float g_a1 [(size_t)BDIM*1024];
__device__ float g_a2 [(size_t)BDIM*512];
__device__ float g_pb1[256], g_pb2[512], g_pb3[1024];
__device__ float g_wx1p[3*256];

// fp16 activations — h ping-pong + BN'd layer outputs
__device__ __half g_hf [(size_t)2*BDIM*LDIM*256];
__device__ __half g_bn1f[(size_t)TDIM*BDIM*LDIM*64];
__device__ __half g_bn2f[(size_t)TDIM*BDIM*LDIM*128];

// fp16 hi/lo weights, [N,K] layout, N gate-interleaved (n' = 4f+g)
__device__ __half g_wh1h[256*192],  g_wh1l[256*192];
__device__ __half g_wx2h[512*192],  g_wx2l[512*192];
__device__ __half g_wh2h[512*384],  g_wh2l[512*384];
__device__ __half g_wx3h[1024*384], g_wx3l[1024*384];
__device__ __half g_wh3h[1024*768], g_wh3l[1024*768];

// ================= helpers =================
__device__ __forceinline__ uint32_t smem_to_u32(const void* p) {
    uint32_t a;
    asm("{ .reg .u64 t; cvta.to.shared.u64 t, %1; cvt.u32.u64 %0, t; }" : "=r"(a) : "l"(p));
    return a;
}
__device__ __forceinline__ void cp_async16(uint32_t saddr, const void* gaddr, uint32_t sz) {
    asm volatile("cp.async.cg.shared.global [%0], [%1], 16, %2;"
                 :: "r"(saddr), "l"(gaddr), "r"(sz));
}
#define CP_COMMIT() asm volatile("cp.async.commit_group;" ::: "memory")
#define CP_WAIT(n)  asm volatile("cp.async.wait_group %0;" :: "n"(n) : "memory")
#define LDSM_X4(r, addr) \
    asm volatile("ldmatrix.sync.aligned.m8n8.x4.shared.b16 {%0,%1,%2,%3}, [%4];" \
        : "=r"((r)[0]), "=r"((r)[1]), "=r"((r)[2]), "=r"((r)[3]) : "r"(addr))

__device__ __forceinline__ void mma16816(float* c, const uint32_t* a,
                                         uint32_t b0, uint32_t b1) {
    asm volatile("mma.sync.aligned.m16n8k16.row.col.f32.f16.f16.f32 "
        "{%0,%1,%2,%3}, {%4,%5,%6,%7}, {%8,%9}, {%0,%1,%2,%3};"
        : "+f"(c[0]), "+f"(c[1]), "+f"(c[2]), "+f"(c[3])
        : "r"(a[0]), "r"(a[1]), "r"(a[2]), "r"(a[3]), "r"(b0), "r"(b1));
}
__device__ __forceinline__ float hsig(float x) {
    return fminf(fmaxf(0.2f * x + 0.5f, 0.f), 1.f);
}

#define SROW  80
#define TILE  (128*SROW)   // 10240
#define BUFSZ (3*TILE)     // A, Bhi, Blo
#define STROW 132          // fp32 staging row stride (floats)

// --- shared mainloop body ---
// C[M,N] = gather3(A)[M,K] @ (Bhi+Blo)[N,K]^T ; A fp16 single, B fp16 hi/lo.
#define MMA_MAINLOOP_BODY \
    const uint32_t sb = smem_to_u32(smem); \
    const int tid  = threadIdx.x; \
    const int wid  = tid >> 5; \
    const int lane = tid & 31; \
    const int wm   = wid >> 1; \
    const int wn   = wid & 1; \
    const int m0   = blockIdx.y * 128; \
    const int n0   = blockIdx.x * 128; \
    const int Cin  = 1 << logCin; \
    const int nk   = K >> 5; \
    float acc[2][8][4]; \
    _Pragma("unroll") \
    for (int mt = 0; mt < 2; mt++) \
        _Pragma("unroll") \
        for (int nt = 0; nt < 8; nt++) \
            _Pragma("unroll") \
            for (int r = 0; r < 4; r++) acc[mt][nt][r] = 0.f; \
    auto load_chunk = [&](int c, int buf) { \
        const int k0  = c << 5; \
        const int ks  = k0 >> logCin; \
        const int ci0 = k0 & (Cin - 1); \
        const uint32_t sbuf = sb + buf * BUFSZ; \
        _Pragma("unroll") \
        for (int i = 0; i < 2; i++) { \
            int idx = tid + (i << 8); \
            int row = idx >> 2; \
            int seg = idx & 3; \
            int m  = m0 + row; \
            int l  = m & (LDIM - 1); \
            int ll = l + ks - 1; \
            uint32_t sz = (ll >= 0 && ll < LDIM) ? 16u : 0u; \
            int llc = ll < 0 ? 0 : (ll > LDIM - 1 ? LDIM - 1 : ll); \
            size_t aoff = (size_t)(m - l + llc) * Cin + ci0 + seg * 8; \
            uint32_t sa = sbuf + row * SROW + seg * 16; \
            cp_async16(sa, Af + aoff, sz); \
            size_t boff = (size_t)(n0 + row) * K + k0 + seg * 8; \
            cp_async16(sa + TILE,     Bhi + boff, 16u); \
            cp_async16(sa + 2 * TILE, Blo + boff, 16u); \
        } \
    }; \
    const int a_row = lane & 15; \
    const int a_k16 = (lane & 16) ? 16 : 0; \
    const int b_row = (lane & 7) + ((lane & 16) ? 8 : 0); \
    const int b_k16 = (lane & 8) ? 16 : 0; \
    load_chunk(0, 0); \
    CP_COMMIT(); \
    for (int c = 0; c < nk; c++) { \
        if (c + 1 < nk) { \
            load_chunk(c + 1, (c + 1) & 1); \
            CP_COMMIT(); \
            CP_WAIT(1); \
        } else { \
            CP_WAIT(0); \
        } \
        __syncthreads(); \
        const uint32_t sbuf = sb + (c & 1) * BUFSZ; \
        _Pragma("unroll") \
        for (int ks = 0; ks < 2; ks++) { \
            uint32_t ah[2][4]; \
            _Pragma("unroll") \
            for (int mt = 0; mt < 2; mt++) { \
                uint32_t ad = sbuf + (wm * 32 + mt * 16 + a_row) * SROW \
                                   + ks * 32 + a_k16; \
                LDSM_X4(ah[mt], ad); \
            } \
            _Pragma("unroll") \
            for (int n2 = 0; n2 < 4; n2++) { \
                uint32_t bd = sbuf + TILE \
                            + (wn * 64 + n2 * 16 + b_row) * SROW \
                            + ks * 32 + b_k16; \
                uint32_t bh[4], bl[4]; \
                LDSM_X4(bh, bd); \
                LDSM_X4(bl, bd + TILE); \
                _Pragma("unroll") \
                for (int mt = 0; mt < 2; mt++) { \
                    mma16816(acc[mt][n2 * 2],     ah[mt], bh[0], bh[1]); \
                    mma16816(acc[mt][n2 * 2],     ah[mt], bl[0], bl[1]); \
                    mma16816(acc[mt][n2 * 2 + 1], ah[mt], bh[2], bh[3]); \
                    mma16816(acc[mt][n2 * 2 + 1], ah[mt], bl[2], bl[3]); \
                } \
            } \
        } \
        __syncthreads(); \
    }

// ================= input-conv GEMM: +bias, store C =================
__global__ __launch_bounds__(256) void mma_gemm_bias(
    const __half* __restrict__ Af,
    const __half* __restrict__ Bhi, const __half* __restrict__ Blo,
    const float* __restrict__ bias, float* __restrict__ C,
    int M, int N, int K, int logCin)
{
    extern __shared__ char smem[];
    MMA_MAINLOOP_BODY

    const int r0 = lane >> 2;
    const int q  = lane & 3;
    const int cp = q * 2;
    #pragma unroll
    for (int mt = 0; mt < 2; mt++) {
        #pragma unroll
        for (int nt = 0; nt < 8; nt++) {
            int row = m0 + wm * 32 + mt * 16 + r0;
            int col = n0 + wn * 64 + nt * 8 + cp;
            float bx = bias[col], by = bias[col + 1];
            float2 v0 = make_float2(acc[mt][nt][0] + bx, acc[mt][nt][1] + by);
            float2 v1 = make_float2(acc[mt][nt][2] + bx, acc[mt][nt][3] + by);
            *reinterpret_cast<float2*>(C + (size_t)row * N + col)       = v0;
            *reinterpret_cast<float2*>(C + (size_t)(row + 8) * N + col) = v1;
        }
    }
}

// ================= recurrent GEMM + fused LSTM gate =================
// Reads prev-step h (Af), writes NEW fp16 buffer (hDst) — no WAR race.
__global__ __launch_bounds__(256) void mma_gemm_gate(
    const __half* __restrict__ Af,
    const __half* __restrict__ Bhi, const __half* __restrict__ Blo,
    const float* __restrict__ xg, float* __restrict__ cst,
    float* __restrict__ hseq, __half* __restrict__ hDst,
    int M, int N, int K, int logCin)
{
    extern __shared__ char smem[];
    MMA_MAINLOOP_BODY

    const int r0 = lane >> 2;
    const int q  = lane & 3;
    // ---- stage accumulators into SMEM (fp32, row stride STROW) ----
    float* st = reinterpret_cast<float*>(smem);
    #pragma unroll
    for (int mt = 0; mt < 2; mt++) {
        #pragma unroll
        for (int nt = 0; nt < 8; nt++) {
            int row_l = wm * 32 + mt * 16 + r0;
            int col_l = wn * 64 + nt * 8 + q * 2;
            *reinterpret_cast<float2*>(&st[row_l * STROW + col_l]) =
                make_float2(acc[mt][nt][0], acc[mt][nt][1]);
            *reinterpret_cast<float2*>(&st[(row_l + 8) * STROW + col_l]) =
                make_float2(acc[mt][nt][2], acc[mt][nt][3]);
        }
    }
    __syncthreads();
    // ---- coalesced gate pass: warp = row, lanes sweep 32 features ----
    const int F = N >> 2;
    const int f0 = n0 >> 2;
    #pragma unroll
    for (int i = 0; i < 16; i++) {
        int e   = tid + (i << 8);
        int row = e >> 5;
        int f   = e & 31;
        float4 g4 = *reinterpret_cast<const float4*>(&st[row * STROW + 4 * f]);
        int m = m0 + row;
        float4 x4 = *reinterpret_cast<const float4*>(xg + (size_t)m * N + n0 + 4 * f);
        float iv = g4.x + x4.x;
        float fv = g4.y + x4.y;
        float cv = g4.z + x4.z;
        float ov = g4.w + x4.w;
        size_t sidx = (size_t)m * F + f0 + f;
        float cn = hsig(fv) * cst[sidx] + hsig(iv) * fmaxf(cv, 0.f);
        cst[sidx] = cn;
        float hn = hsig(ov) * fmaxf(cn, 0.f);
        hseq[sidx] = hn;
        hDst[sidx] = __float2half(hn);
    }
}

// ===== t=0 gate (h=c=0): c = hsig(i)*relu(cg); also initializes cst/h buffers =====
__global__ void gate0_kernel(const float4* __restrict__ xg, float* __restrict__ cst,
                             float* __restrict__ hseq,
                             __half* __restrict__ hf, int total)
{
    int idx = blockIdx.x * blockDim.x + threadIdx.x;
    if (idx >= total) return;
    float4 x4 = xg[idx];
    float cn = hsig(x4.x) * fmaxf(x4.z, 0.f);
    cst[idx] = cn;
    float hn = hsig(x4.w) * fmaxf(cn, 0.f);
    hseq[idx] = hn;
    hf[idx] = __float2half(hn);
}

// ===== weight convert: W[K,N] fp32 -> [N',K] fp16 hi/lo with gate interleave =====
__global__ void wconv_kernel(const float* __restrict__ W,
                             __half* __restrict__ Bh, __half* __restrict__ Bl,
                             int K, int N)
{
    int idx = blockIdx.x * blockDim.x + threadIdx.x;
    if (idx >= N * K) return;
    int np = idx / K, k = idx - np * K;
    int F = N >> 2;
    int n = (np & 3) * F + (np >> 2);
    float x = W[(size_t)k * N + n];
    __half hi = __float2half(x);
    Bh[idx] = hi;
    Bl[idx] = __float2half(x - __half2float(hi));
}

// ===== bias permute: pb[4f+g] = b[g*F+f] =====
__global__ void permute_bias(const float* __restrict__ b, float* __restrict__ pb, int N)
{
    int idx = blockIdx.x * blockDim.x + threadIdx.x;
    if (idx >= N) return;
    int F = N >> 2;
    pb[idx] = b[(idx & 3) * F + (idx >> 2)];
}

// ===== permute Wx1 [3,256] fp32 -> gate-interleaved cols =====
__global__ void permute_wx1(const float* __restrict__ W, float* __restrict__ Wp)
{
    int idx = blockIdx.x * blockDim.x + threadIdx.x;
    if (idx >= 3 * 256) return;
    int k = idx >> 8, np = idx & 255;
    Wp[idx] = W[k * 256 + (np & 3) * 64 + (np >> 2)];
}

// ================= fp32 implicit GEMM (layer-1 input, K=3), T-major output ========
#define BM 128
#define BN 128
#define BK 8
__global__ __launch_bounds__(256) void gemm_conv_kernel(
    const float* __restrict__ A, const float* __restrict__ W,
    const float* __restrict__ bias, float* __restrict__ C,
    int M, int N, int K, int logCin)
{
    __shared__ float As[BK][BM];
    __shared__ float Bs[BK][BN];
    int tid = threadIdx.x;
    int m0 = blockIdx.y * BM;
    int n0 = blockIdx.x * BN;
    int tx = tid & 15, ty = tid >> 4;
    int a_row = tid >> 1;
    int a_col = (tid & 1) * 4;
    int b_k = tid >> 5;
    int b_n = (tid & 31) * 4;
    int Cin = 1 << logCin;
    float acc[8][8];
    #pragma unroll
    for (int i = 0; i < 8; i++)
        #pragma unroll
        for (int j = 0; j < 8; j++) acc[i][j] = 0.f;
    for (int k0 = 0; k0 < K; k0 += BK) {
        int m = m0 + a_row;
        #pragma unroll
        for (int i = 0; i < 4; i++) {
            int kk = k0 + a_col + i;
            float v = 0.f;
            if (m < M && kk < K) {
                int l = m & (LDIM - 1);
                int ks = kk >> logCin;
                int ci = kk - (ks << logCin);
                int ll = l + ks - 1;
                if (ll >= 0 && ll < LDIM)
                    v = A[(size_t)(m - l + ll) * Cin + ci];
            }
            As[a_col + i][a_row] = v;
        }
        {
            int kk = k0 + b_k;
            float4 v = make_float4(0.f, 0.f, 0.f, 0.f);
            if (kk < K && n0 + b_n + 3 < N)
                v = *reinterpret_cast<const float4*>(&W[(size_t)kk * N + n0 + b_n]);
            Bs[b_k][b_n] = v.x; Bs[b_k][b_n+1] = v.y; Bs[b_k][b_n+2] = v.z; Bs[b_k][b_n+3] = v.w;
        }
        __syncthreads();
        #pragma unroll
        for (int kk = 0; kk < BK; kk++) {
            float af[8], bf[8];
            #pragma unroll
            for (int i = 0; i < 8; i++) af[i] = As[kk][ty * 8 + i];
            #pragma unroll
            for (int j = 0; j < 8; j++) bf[j] = Bs[kk][tx * 8 + j];
            #pragma unroll
            for (int i = 0; i < 8; i++)
                #pragma unroll
                for (int j = 0; j < 8; j++) acc[i][j] += af[i] * bf[j];
        }
        __syncthreads();
    }
    #pragma unroll
    for (int i = 0; i < 8; i++) {
        int m = m0 + ty * 8 + i;
        if (m >= M) continue;
        int l = m & (LDIM - 1);
        int bt = m >> LOG_L;
        int b = bt >> 5;
        int t = bt & 31;
        int mp = ((t << 5) + b) * LDIM + l;
        #pragma unroll
        for (int j = 0; j < 8; j++) {
            int n = n0 + tx * 8 + j;
            if (n >= N) continue;
            float v = acc[i][j];
            if (bias) v += bias[n];
            C[(size_t)mp * N + n] = v;
        }
    }
}

// ================= BN (fp32 in place) =================
__global__ void bn_kernel(float* __restrict__ x, const float* __restrict__ gw,
                          const float* __restrict__ be, const float* __restrict__ mu,
                          const float* __restrict__ var, size_t total, int logC)
{
    size_t idx = (size_t)blockIdx.x * blockDim.x + threadIdx.x;
    if (idx >= total) return;
    int C = 1 << logC;
    int ch = (int)(idx & (size_t)(C - 1));
    x[idx] = (x[idx] - mu[ch]) * rsqrtf(var[ch] + 1e-3f) * gw[ch] + be[ch];
}

// ================= BN -> fp16 convert =================
__global__ void bn_convert(const float* __restrict__ x, const float* __restrict__ gw,
                           const float* __restrict__ be, const float* __restrict__ mu,
                           const float* __restrict__ var,
                           __half* __restrict__ of, size_t total, int logC)
{
    size_t idx = (size_t)blockIdx.x * blockDim.x + threadIdx.x;
    if (idx >= total) return;
    int C = 1 << logC;
    int ch = (int)(idx & (size_t)(C - 1));
    float v = (x[idx] - mu[ch]) * rsqrtf(var[ch] + 1e-3f) * gw[ch] + be[ch];
    of[idx] = __float2half(v);
}

// ================= dense head (fp32, small) =================
__global__ __launch_bounds__(256) void fc_kernel(
    const float* __restrict__ A, const float* __restrict__ W,
    float* __restrict__ partial, int N, int K, int kchunk)
{
    __shared__ float As[32][33];
    int tid = threadIdx.x;
    int n0 = blockIdx.x * 64;
    int col = tid & 63;
    int rq = tid >> 6;
    int k0 = blockIdx.y * kchunk;
    int kend = min(K, k0 + kchunk);
    float acc[8];
    #pragma unroll
    for (int r = 0; r < 8; r++) acc[r] = 0.f;
    int a_m = tid >> 3;
    int a_k = (tid & 7) * 4;
    for (int kb = k0; kb < kend; kb += 32) {
        #pragma unroll
        for (int i = 0; i < 4; i++) {
            int kk = kb + a_k + i;
            As[a_m][a_k + i] = (kk < K) ? A[(size_t)a_m * K + kk] : 0.f;
        }
        __syncthreads();
        #pragma unroll
        for (int kk = 0; kk < 32; kk++) {
            float w = W[(size_t)(kb + kk) * N + n0 + col];
            #pragma unroll
            for (int r = 0; r < 8; r++) acc[r] += As[rq * 8 + r][kk] * w;
        }
        __syncthreads();
    }
    #pragma unroll
    for (int r = 0; r < 8; r++) {
        int m = rq * 8 + r;
        partial[((size_t)blockIdx.y * 32 + m) * N + n0 + col] = acc[r];
    }
}

__global__ void fc_reduce_relu(const float* __restrict__ partial,
                               const float* __restrict__ bias,
                               float* __restrict__ out, int N, int KS)
{
    int idx = blockIdx.x * blockDim.x + threadIdx.x;
    if (idx >= 32 * N) return;
    int m = idx / N, n = idx - m * N;
    float s = bias[n];
    for (int ks = 0; ks < KS; ks++)
        s += partial[((size_t)ks * 32 + m) * N + n];
    out[idx] = fmaxf(s, 0.f);
}

__global__ void fc3_softmax(const float* __restrict__ A, const float* __restrict__ W,
                            const float* __restrict__ bias, float* __restrict__ out)
{
    __shared__ float logits[32][5];
    int tid = threadIdx.x;
    int bm = tid >> 3, j = tid & 7;
    if (bm < 32 && j < 5) {
        float s = bias[j];
        for (int k = 0; k < 512; k++)
            s += A[bm * 512 + k] * W[k * 5 + j];
        logits[bm][j] = s;
    }
    __syncthreads();
    if (bm < 32 && j == 0) {
        float mx = logits[bm][0];
        for (int q = 1; q < 5; q++) mx = fmaxf(mx, logits[bm][q]);
        float e[5], sum = 0.f;
        for (int q = 0; q < 5; q++) { e[q] = expf(logits[bm][q] - mx); sum += e[q]; }
        for (int q = 0; q < 5; q++) out[bm * 5 + q] = e[q] / sum;
    }
}

// ================= host orchestration =================
extern "C" void kernel_launch(void* const* d_in, const int* in_sizes, int n_in,
                              void* d_out, int out_size)
{
    const float* x   = (const float*)d_in[0];
    const float* Wx1 = (const float*)d_in[1];
    const float* Wh1 = (const float*)d_in[2];
    const float* b1  = (const float*)d_in[3];
    const float* Wx2 = (const float*)d_in[4];
    const float* Wh2 = (const float*)d_in[5];
    const float* b2  = (const float*)d_in[6];
    const float* Wx3 = (const float*)d_in[7];
    const float* Wh3 = (const float*)d_in[8];
    const float* b3  = (const float*)d_in[9];
    const float* g1  = (const float*)d_in[10];
    const float* be1 = (const float*)d_in[11];
    const float* m1  = (const float*)d_in[12];
    const float* v1  = (const float*)d_in[13];
    const float* g2  = (const float*)d_in[14];
    const float* be2 = (const float*)d_in[15];
    const float* m2  = (const float*)d_in[16];
    const float* v2  = (const float*)d_in[17];
    const float* g3  = (const float*)d_in[18];
    const float* be3 = (const float*)d_in[19];
    const float* m3  = (const float*)d_in[20];
    const float* v3  = (const float*)d_in[21];
    const float* D1  = (const float*)d_in[22];
    const float* db1 = (const float*)d_in[23];
    const float* D2  = (const float*)d_in[24];
    const float* db2 = (const float*)d_in[25];
    const float* D3  = (const float*)d_in[26];
    const float* db3 = (const float*)d_in[27];
    float* out = (float*)d_out;

    float *xg1, *xg2, *xg3, *h1, *h2, *hst, *cst, *prt, *a1, *a2;
    float *pb1, *pb2, *pb3, *wx1p;
    __half *hf, *bn1f, *bn2f;
    __half *wh1h, *wh1l, *wx2h, *wx2l, *wh2h, *wh2l, *wx3h, *wx3l, *wh3h, *wh3l;
    cudaGetSymbolAddress((void**)&xg1, g_xg1);
    cudaGetSymbolAddress((void**)&xg2, g_xg2);
    cudaGetSymbolAddress((void**)&xg3, g_xg3);
    cudaGetSymbolAddress((void**)&h1,  g_h1);
    cudaGetSymbolAddress((void**)&h2,  g_h2);
    cudaGetSymbolAddress((void**)&hst, g_hst);
    cudaGetSymbolAddress((void**)&cst, g_cst);
    cudaGetSymbolAddress((void**)&prt, g_prt);
    cudaGetSymbolAddress((void**)&a1,  g_a1);
    cudaGetSymbolAddress((void**)&a2,  g_a2);
    cudaGetSymbolAddress((void**)&pb1, g_pb1);
    cudaGetSymbolAddress((void**)&pb2, g_pb2);
    cudaGetSymbolAddress((void**)&pb3, g_pb3);
    cudaGetSymbolAddress((void**)&wx1p, g_wx1p);
    cudaGetSymbolAddress((void**)&hf,   g_hf);
    cudaGetSymbolAddress((void**)&bn1f, g_bn1f);
    cudaGetSymbolAddress((void**)&bn2f, g_bn2f);
    cudaGetSymbolAddress((void**)&wh1h, g_wh1h); cudaGetSymbolAddress((void**)&wh1l, g_wh1l);
    cudaGetSymbolAddress((void**)&wx2h, g_wx2h); cudaGetSymbolAddress((void**)&wx2l, g_wx2l);
    cudaGetSymbolAddress((void**)&wh2h, g_wh2h); cudaGetSymbolAddress((void**)&wh2l, g_wh2l);
    cudaGetSymbolAddress((void**)&wx3h, g_wx3h); cudaGetSymbolAddress((void**)&wx3l, g_wx3l);
    cudaGetSymbolAddress((void**)&wh3h, g_wh3h); cudaGetSymbolAddress((void**)&wh3l, g_wh3l);

    const int Mall = BDIM * TDIM * LDIM;   // 131072
    const int Mst  = BDIM * LDIM;          // 4096
    const size_t HBUF = (size_t)BDIM * LDIM * 256;   // ping-pong stride (elems)
    const int SMEM_BIAS = 2 * BUFSZ;                 // 61440
    const int SMEM_GATE = 128 * STROW * 4;           // 67584 (> 2*BUFSZ)
    cudaFuncSetAttribute(mma_gemm_bias, cudaFuncAttributeMaxDynamicSharedMemorySize, SMEM_BIAS);
    cudaFuncSetAttribute(mma_gemm_gate, cudaFuncAttributeMaxDynamicSharedMemorySize, SMEM_GATE);
    dim3 blk(256);

    // ---- weight/bias conversions (gate-interleaved) ----
    wconv_kernel<<<(256*192  + 255)/256, 256>>>(Wh1, wh1h, wh1l, 192, 256);
    wconv_kernel<<<(512*192  + 255)/256, 256>>>(Wx2, wx2h, wx2l, 192, 512);
    wconv_kernel<<<(512*384  + 255)/256, 256>>>(Wh2, wh2h, wh2l, 384, 512);
    wconv_kernel<<<(1024*384 + 255)/256, 256>>>(Wx3, wx3h, wx3l, 384, 1024);
    wconv_kernel<<<(1024*768 + 255)/256, 256>>>(Wh3, wh3h, wh3l, 768, 1024);
    permute_bias<<<1, 256>>>(b1, pb1, 256);
    permute_bias<<<2, 256>>>(b2, pb2, 512);
    permute_bias<<<4, 256>>>(b3, pb3, 1024);
    permute_wx1<<<3, 256>>>(Wx1, wx1p);

    // ================= Layer 1 =================
    gemm_conv_kernel<<<dim3(2, Mall / BM), blk>>>(x, wx1p, pb1, xg1, Mall, 256, 3, 0);
    gate0_kernel<<<(Mst * 64 + 255) / 256, 256>>>(
        (const float4*)xg1, cst, h1, hf, Mst * 64);
    for (int t = 1; t < TDIM; t++) {
        int pi = (t - 1) & 1, po = t & 1;
        mma_gemm_gate<<<dim3(2, Mst / 128), blk, SMEM_GATE>>>(
            hf + pi * HBUF, wh1h, wh1l,
            xg1 + (size_t)t * Mst * 256, cst, h1 + (size_t)t * Mst * 64,
            hf + po * HBUF,
            Mst, 256, 192, 6);
    }
    {
        size_t tot = (size_t)TDIM * Mst * 64;
        bn_convert<<<(int)((tot + 255) / 256), 256>>>(h1, g1, be1, m1, v1, bn1f, tot, 6);
    }

    // ================= Layer 2 =================
    mma_gemm_bias<<<dim3(4, Mall / 128), blk, SMEM_BIAS>>>(
        bn1f, wx2h, wx2l, pb2, xg2, Mall, 512, 192, 6);
    gate0_kernel<<<(Mst * 128 + 255) / 256, 256>>>(
        (const float4*)xg2, cst, h2, hf, Mst * 128);
    for (int t = 1; t < TDIM; t++) {
        int pi = (t - 1) & 1, po = t & 1;
        mma_gemm_gate<<<dim3(4, Mst / 128), blk, SMEM_GATE>>>(
            hf + pi * HBUF, wh2h, wh2l,
            xg2 + (size_t)t * Mst * 512, cst, h2 + (size_t)t * Mst * 128,
            hf + po * HBUF,
            Mst, 512, 384, 7);
    }
    {
        size_t tot = (size_t)TDIM * Mst * 128;
        bn_convert<<<(int)((tot + 255) / 256), 256>>>(h2, g2, be2, m2, v2, bn2f, tot, 7);
    }

    // ================= Layer 3 =================
    mma_gemm_bias<<<dim3(8, Mall / 128), blk, SMEM_BIAS>>>(
        bn2f, wx3h, wx3l, pb3, xg3, Mall, 1024, 384, 7);
    gate0_kernel<<<(Mst * 256 + 255) / 256, 256>>>(
        (const float4*)xg3, cst, hst, hf, Mst * 256);
    for (int t = 1; t < TDIM; t++) {
        int pi = (t - 1) & 1, po = t & 1;
        mma_gemm_gate<<<dim3(8, Mst / 128), blk, SMEM_GATE>>>(
            hf + pi * HBUF, wh3h, wh3l,
            xg3 + (size_t)t * Mst * 1024, cst, hst,
            hf + po * HBUF,
            Mst, 1024, 768, 8);
    }
    {
        size_t tot = (size_t)Mst * 256;
        bn_kernel<<<(int)((tot + 255) / 256), 256>>>(hst, g3, be3, m3, v3, tot, 8);
    }

    // ================= Dense head =================
    fc_kernel<<<dim3(1024 / 64, 8), blk>>>(hst, D1, prt, 1024, 32768, 4096);
    fc_reduce_relu<<<(32 * 1024 + 255) / 256, 256>>>(prt, db1, a1, 1024, 8);
    fc_kernel<<<dim3(512 / 64, 2), blk>>>(a1, D2, prt, 512, 1024, 512);
    fc_reduce_relu<<<(32 * 512 + 255) / 256, 256>>>(prt, db2, a2, 512, 2);
    fc3_softmax<<<1, 256>>>(a2, D3, db3, out);
}

// round 17
// speedup vs baseline: 2.0033x; 1.3412x over previous
#include <cuda_runtime.h>
#include <cuda_fp16.h>
#include <math.h>
#include <cstdint>

#define BDIM 32
#define TDIM 32
#define LDIM 128
#define LOG_L 7

// ================= scratch (static device globals) =================
__device__ float g_xg1[(size_t)TDIM*BDIM*LDIM*256];   // [T][B][L][4F1] (gate-interleaved)
__device__ float g_xg2[(size_t)TDIM*BDIM*LDIM*512];   // [T][B][L][4F2]
__device__ float g_xg3[(size_t)TDIM*BDIM*LDIM*1024];  // [T][B][L][4F3]
__device__ float g_hst[(size_t)BDIM*LDIM*256];
__device__ float g_cst[(size_t)BDIM*LDIM*256];
__device__ float g_prt[(size_t)8*BDIM*1024];
__device__ float g_a1 [(size_t)BDIM*1024];
__device__ float g_a2 [(size_t)BDIM*512];
__device__ float g_pb1[256], g_pb2[512], g_pb3[1024];
__device__ float g_wx1p[3*256];
__device__ float g_sc1[64],  g_sh1[64];
__device__ float g_sc2[128], g_sh2[128];

// fp16 activations — h ping-pong + BN'd layer outputs (input of next layer)
__device__ __half g_hf  [(size_t)2*BDIM*LDIM*256];
__device__ __half g_bn1f[(size_t)TDIM*BDIM*LDIM*64];
__device__ __half g_bn2f[(size_t)TDIM*BDIM*LDIM*128];

// fp16 weights, [N,K] layout, N gate-interleaved (n' = 4f+g)
__device__ __half g_wh1[256*192];
__device__ __half g_wx2[512*192];
__device__ __half g_wh2[512*384];
__device__ __half g_wx3[1024*384];
__device__ __half g_wh3[1024*768];

// ================= helpers =================
__device__ __forceinline__ uint32_t smem_to_u32(const void* p) {
    uint32_t a;
    asm("{ .reg .u64 t; cvta.to.shared.u64 t, %1; cvt.u32.u64 %0, t; }" : "=r"(a) : "l"(p));
    return a;
}
__device__ __forceinline__ void cp_async16(uint32_t saddr, const void* gaddr, uint32_t sz) {
    asm volatile("cp.async.cg.shared.global [%0], [%1], 16, %2;"
                 :: "r"(saddr), "l"(gaddr), "r"(sz));
}
#define CP_COMMIT() asm volatile("cp.async.commit_group;" ::: "memory")
#define CP_WAIT(n)  asm volatile("cp.async.wait_group %0;" :: "n"(n) : "memory")
#define LDSM_X4(r, addr) \
    asm volatile("ldmatrix.sync.aligned.m8n8.x4.shared.b16 {%0,%1,%2,%3}, [%4];" \
        : "=r"((r)[0]), "=r"((r)[1]), "=r"((r)[2]), "=r"((r)[3]) : "r"(addr))

__device__ __forceinline__ void mma16816(float* c, const uint32_t* a,
                                         uint32_t b0, uint32_t b1) {
    asm volatile("mma.sync.aligned.m16n8k16.row.col.f32.f16.f16.f32 "
        "{%0,%1,%2,%3}, {%4,%5,%6,%7}, {%8,%9}, {%0,%1,%2,%3};"
        : "+f"(c[0]), "+f"(c[1]), "+f"(c[2]), "+f"(c[3])
        : "r"(a[0]), "r"(a[1]), "r"(a[2]), "r"(a[3]), "r"(b0), "r"(b1));
}
__device__ __forceinline__ float hsig(float x) {
    return fminf(fmaxf(0.2f * x + 0.5f, 0.f), 1.f);
}

#define SROW  80
#define TILE  (128*SROW)   // 10240
#define BUFSZ (2*TILE)     // A, B
#define STROW 132          // fp32 staging row stride (floats)

// --- shared mainloop body ---
// C[M,N] = gather3(A)[M,K] @ B[N,K]^T ; A,B single fp16.
#define MMA_MAINLOOP_BODY \
    const uint32_t sb = smem_to_u32(smem); \
    const int tid  = threadIdx.x; \
    const int wid  = tid >> 5; \
    const int lane = tid & 31; \
    const int wm   = wid >> 1; \
    const int wn   = wid & 1; \
    const int m0   = blockIdx.y * 128; \
    const int n0   = blockIdx.x * 128; \
    const int Cin  = 1 << logCin; \
    const int nk   = K >> 5; \
    float acc[2][8][4]; \
    _Pragma("unroll") \
    for (int mt = 0; mt < 2; mt++) \
        _Pragma("unroll") \
        for (int nt = 0; nt < 8; nt++) \
            _Pragma("unroll") \
            for (int r = 0; r < 4; r++) acc[mt][nt][r] = 0.f; \
    auto load_chunk = [&](int c, int buf) { \
        const int k0  = c << 5; \
        const int ks  = k0 >> logCin; \
        const int ci0 = k0 & (Cin - 1); \
        const uint32_t sbuf = sb + buf * BUFSZ; \
        _Pragma("unroll") \
        for (int i = 0; i < 2; i++) { \
            int idx = tid + (i << 8); \
            int row = idx >> 2; \
            int seg = idx & 3; \
            int m  = m0 + row; \
            int l  = m & (LDIM - 1); \
            int ll = l + ks - 1; \
            uint32_t sz = (ll >= 0 && ll < LDIM) ? 16u : 0u; \
            int llc = ll < 0 ? 0 : (ll > LDIM - 1 ? LDIM - 1 : ll); \
            size_t aoff = (size_t)(m - l + llc) * Cin + ci0 + seg * 8; \
            uint32_t sa = sbuf + row * SROW + seg * 16; \
            cp_async16(sa, Af + aoff, sz); \
            size_t boff = (size_t)(n0 + row) * K + k0 + seg * 8; \
            cp_async16(sa + TILE, Bf + boff, 16u); \
        } \
    }; \
    const int a_row = lane & 15; \
    const int a_k16 = (lane & 16) ? 16 : 0; \
    const int b_row = (lane & 7) + ((lane & 16) ? 8 : 0); \
    const int b_k16 = (lane & 8) ? 16 : 0; \
    load_chunk(0, 0); \
    CP_COMMIT(); \
    for (int c = 0; c < nk; c++) { \
        if (c + 1 < nk) { \
            load_chunk(c + 1, (c + 1) & 1); \
            CP_COMMIT(); \
            CP_WAIT(1); \
        } else { \
            CP_WAIT(0); \
        } \
        __syncthreads(); \
        const uint32_t sbuf = sb + (c & 1) * BUFSZ; \
        _Pragma("unroll") \
        for (int ks = 0; ks < 2; ks++) { \
            uint32_t ah[2][4]; \
            _Pragma("unroll") \
            for (int mt = 0; mt < 2; mt++) { \
                uint32_t ad = sbuf + (wm * 32 + mt * 16 + a_row) * SROW \
                                   + ks * 32 + a_k16; \
                LDSM_X4(ah[mt], ad); \
            } \
            _Pragma("unroll") \
            for (int n2 = 0; n2 < 4; n2++) { \
                uint32_t bd = sbuf + TILE \
                            + (wn * 64 + n2 * 16 + b_row) * SROW \
                            + ks * 32 + b_k16; \
                uint32_t bh[4]; \
                LDSM_X4(bh, bd); \
                _Pragma("unroll") \
                for (int mt = 0; mt < 2; mt++) { \
                    mma16816(acc[mt][n2 * 2],     ah[mt], bh[0], bh[1]); \
                    mma16816(acc[mt][n2 * 2 + 1], ah[mt], bh[2], bh[3]); \
                } \
            } \
        } \
        __syncthreads(); \
    }

// ================= input-conv GEMM: +bias, store C =================
__global__ __launch_bounds__(256) void mma_gemm_bias(
    const __half* __restrict__ Af, const __half* __restrict__ Bf,
    const float* __restrict__ bias, float* __restrict__ C,
    int M, int N, int K, int logCin)
{
    extern __shared__ char smem[];
    MMA_MAINLOOP_BODY

    const int r0 = lane >> 2;
    const int q  = lane & 3;
    const int cp = q * 2;
    #pragma unroll
    for (int mt = 0; mt < 2; mt++) {
        #pragma unroll
        for (int nt = 0; nt < 8; nt++) {
            int row = m0 + wm * 32 + mt * 16 + r0;
            int col = n0 + wn * 64 + nt * 8 + cp;
            float bx = bias[col], by = bias[col + 1];
            float2 v0 = make_float2(acc[mt][nt][0] + bx, acc[mt][nt][1] + by);
            float2 v1 = make_float2(acc[mt][nt][2] + bx, acc[mt][nt][3] + by);
            *reinterpret_cast<float2*>(C + (size_t)row * N + col)       = v0;
            *reinterpret_cast<float2*>(C + (size_t)(row + 8) * N + col) = v1;
        }
    }
}

// ================= recurrent GEMM + fused LSTM gate (+optional fused BN) ========
// Reads prev-step h (Af), writes NEW fp16 buffer (hDst) — no WAR race.
// bnsc!=null: writes BN'd fp16 to bnDst. hseq!=null: writes raw fp32 h.
__global__ __launch_bounds__(256) void mma_gemm_gate(
    const __half* __restrict__ Af, const __half* __restrict__ Bf,
    const float* __restrict__ xg, float* __restrict__ cst,
    __half* __restrict__ hDst,
    const float* __restrict__ bnsc, const float* __restrict__ bnsh,
    __half* __restrict__ bnDst, float* __restrict__ hseq,
    int M, int N, int K, int logCin)
{
    extern __shared__ char smem[];
    MMA_MAINLOOP_BODY

    const int r0 = lane >> 2;
    const int q  = lane & 3;
    // ---- stage accumulators into SMEM (fp32, row stride STROW) ----
    float* st = reinterpret_cast<float*>(smem);
    #pragma unroll
    for (int mt = 0; mt < 2; mt++) {
        #pragma unroll
        for (int nt = 0; nt < 8; nt++) {
            int row_l = wm * 32 + mt * 16 + r0;
            int col_l = wn * 64 + nt * 8 + q * 2;
            *reinterpret_cast<float2*>(&st[row_l * STROW + col_l]) =
                make_float2(acc[mt][nt][0], acc[mt][nt][1]);
            *reinterpret_cast<float2*>(&st[(row_l + 8) * STROW + col_l]) =
                make_float2(acc[mt][nt][2], acc[mt][nt][3]);
        }
    }
    __syncthreads();
    // ---- coalesced gate pass: warp = row, lanes sweep 32 features ----
    const int F = N >> 2;
    const int f0 = n0 >> 2;
    #pragma unroll
    for (int i = 0; i < 16; i++) {
        int e   = tid + (i << 8);
        int row = e >> 5;
        int f   = e & 31;
        float4 g4 = *reinterpret_cast<const float4*>(&st[row * STROW + 4 * f]);
        int m = m0 + row;
        float4 x4 = *reinterpret_cast<const float4*>(xg + (size_t)m * N + n0 + 4 * f);
        float iv = g4.x + x4.x;
        float fv = g4.y + x4.y;
        float cv = g4.z + x4.z;
        float ov = g4.w + x4.w;
        size_t sidx = (size_t)m * F + f0 + f;
        float cn = hsig(fv) * cst[sidx] + hsig(iv) * fmaxf(cv, 0.f);
        cst[sidx] = cn;
        float hn = hsig(ov) * fmaxf(cn, 0.f);
        hDst[sidx] = __float2half(hn);
        if (bnsc) {
            int fg = f0 + f;
            bnDst[sidx] = __float2half(hn * bnsc[fg] + bnsh[fg]);
        } else if (hseq) {
            hseq[sidx] = hn;
        }
    }
}

// ===== t=0 gate (h=c=0): c = hsig(i)*relu(cg); initializes cst/h (+opt BN) =====
__global__ void gate0_kernel(const float4* __restrict__ xg, float* __restrict__ cst,
                             __half* __restrict__ hf,
                             const float* __restrict__ bnsc,
                             const float* __restrict__ bnsh,
                             __half* __restrict__ bnDst,
                             int total, int logF)
{
    int idx = blockIdx.x * blockDim.x + threadIdx.x;
    if (idx >= total) return;
    float4 x4 = xg[idx];
    float cn = hsig(x4.x) * fmaxf(x4.z, 0.f);
    cst[idx] = cn;
    float hn = hsig(x4.w) * fmaxf(cn, 0.f);
    hf[idx] = __float2half(hn);
    if (bnsc) {
        int f = idx & ((1 << logF) - 1);
        bnDst[idx] = __float2half(hn * bnsc[f] + bnsh[f]);
    }
}

// ===== BN scale/shift precompute =====
__global__ void bn_prep(const float* __restrict__ g, const float* __restrict__ be,
                        const float* __restrict__ mu, const float* __restrict__ var,
                        float* __restrict__ sc, float* __restrict__ sh, int C)
{
    int i = blockIdx.x * blockDim.x + threadIdx.x;
    if (i >= C) return;
    float s = g[i] * rsqrtf(var[i] + 1e-3f);
    sc[i] = s;
    sh[i] = be[i] - mu[i] * s;
}

// ===== weight convert: W[K,N] fp32 -> [N',K] fp16 with gate interleave =====
__global__ void wconv_kernel(const float* __restrict__ W,
                             __half* __restrict__ Bf, int K, int N)
{
    int idx = blockIdx.x * blockDim.x + threadIdx.x;
    if (idx >= N * K) return;
    int np = idx / K, k = idx - np * K;
    int F = N >> 2;
    int n = (np & 3) * F + (np >> 2);
    Bf[idx] = __float2half(W[(size_t)k * N + n]);
}

// ===== bias permute: pb[4f+g] = b[g*F+f] =====
__global__ void permute_bias(const float* __restrict__ b, float* __restrict__ pb, int N)
{
    int idx = blockIdx.x * blockDim.x + threadIdx.x;
    if (idx >= N) return;
    int F = N >> 2;
    pb[idx] = b[(idx & 3) * F + (idx >> 2)];
}

// ===== permute Wx1 [3,256] fp32 -> gate-interleaved cols =====
__global__ void permute_wx1(const float* __restrict__ W, float* __restrict__ Wp)
{
    int idx = blockIdx.x * blockDim.x + threadIdx.x;
    if (idx >= 3 * 256) return;
    int k = idx >> 8, np = idx & 255;
    Wp[idx] = W[k * 256 + (np & 3) * 64 + (np >> 2)];
}

// ================= fp32 implicit GEMM (layer-1 input, K=3), T-major output ========
#define BM 128
#define BN 128
#define BK 8
__global__ __launch_bounds__(256) void gemm_conv_kernel(
    const float* __restrict__ A, const float* __restrict__ W,
    const float* __restrict__ bias, float* __restrict__ C,
    int M, int N, int K, int logCin)
{
    __shared__ float As[BK][BM];
    __shared__ float Bs[BK][BN];
    int tid = threadIdx.x;
    int m0 = blockIdx.y * BM;
    int n0 = blockIdx.x * BN;
    int tx = tid & 15, ty = tid >> 4;
    int a_row = tid >> 1;
    int a_col = (tid & 1) * 4;
    int b_k = tid >> 5;
    int b_n = (tid & 31) * 4;
    int Cin = 1 << logCin;
    float acc[8][8];
    #pragma unroll
    for (int i = 0; i < 8; i++)
        #pragma unroll
        for (int j = 0; j < 8; j++) acc[i][j] = 0.f;
    for (int k0 = 0; k0 < K; k0 += BK) {
        int m = m0 + a_row;
        #pragma unroll
        for (int i = 0; i < 4; i++) {
            int kk = k0 + a_col + i;
            float v = 0.f;
            if (m < M && kk < K) {
                int l = m & (LDIM - 1);
                int ks = kk >> logCin;
                int ci = kk - (ks << logCin);
                int ll = l + ks - 1;
                if (ll >= 0 && ll < LDIM)
                    v = A[(size_t)(m - l + ll) * Cin + ci];
            }
            As[a_col + i][a_row] = v;
        }
        {
            int kk = k0 + b_k;
            float4 v = make_float4(0.f, 0.f, 0.f, 0.f);
            if (kk < K && n0 + b_n + 3 < N)
                v = *reinterpret_cast<const float4*>(&W[(size_t)kk * N + n0 + b_n]);
            Bs[b_k][b_n] = v.x; Bs[b_k][b_n+1] = v.y; Bs[b_k][b_n+2] = v.z; Bs[b_k][b_n+3] = v.w;
        }
        __syncthreads();
        #pragma unroll
        for (int kk = 0; kk < BK; kk++) {
            float af[8], bf[8];
            #pragma unroll
            for (int i = 0; i < 8; i++) af[i] = As[kk][ty * 8 + i];
            #pragma unroll
            for (int j = 0; j < 8; j++) bf[j] = Bs[kk][tx * 8 + j];
            #pragma unroll
            for (int i = 0; i < 8; i++)
                #pragma unroll
                for (int j = 0; j < 8; j++) acc[i][j] += af[i] * bf[j];
        }
        __syncthreads();
    }
    #pragma unroll
    for (int i = 0; i < 8; i++) {
        int m = m0 + ty * 8 + i;
        if (m >= M) continue;
        int l = m & (LDIM - 1);
        int bt = m >> LOG_L;
        int b = bt >> 5;
        int t = bt & 31;
        int mp = ((t << 5) + b) * LDIM + l;
        #pragma unroll
        for (int j = 0; j < 8; j++) {
            int n = n0 + tx * 8 + j;
            if (n >= N) continue;
            float v = acc[i][j];
            if (bias) v += bias[n];
            C[(size_t)mp * N + n] = v;
        }
    }
}

// ================= BN (fp32 in place) =================
__global__ void bn_kernel(float* __restrict__ x, const float* __restrict__ gw,
                          const float* __restrict__ be, const float* __restrict__ mu,
                          const float* __restrict__ var, size_t total, int logC)
{
    size_t idx = (size_t)blockIdx.x * blockDim.x + threadIdx.x;
    if (idx >= total) return;
    int C = 1 << logC;
    int ch = (int)(idx & (size_t)(C - 1));
    x[idx] = (x[idx] - mu[ch]) * rsqrtf(var[ch] + 1e-3f) * gw[ch] + be[ch];
}

// ================= dense head (fp32, small) =================
__global__ __launch_bounds__(256) void fc_kernel(
    const float* __restrict__ A, const float* __restrict__ W,
    float* __restrict__ partial, int N, int K, int kchunk)
{
    __shared__ float As[32][33];
    int tid = threadIdx.x;
    int n0 = blockIdx.x * 64;
    int col = tid & 63;
    int rq = tid >> 6;
    int k0 = blockIdx.y * kchunk;
    int kend = min(K, k0 + kchunk);
    float acc[8];
    #pragma unroll
    for (int r = 0; r < 8; r++) acc[r] = 0.f;
    int a_m = tid >> 3;
    int a_k = (tid & 7) * 4;
    for (int kb = k0; kb < kend; kb += 32) {
        #pragma unroll
        for (int i = 0; i < 4; i++) {
            int kk = kb + a_k + i;
            As[a_m][a_k + i] = (kk < K) ? A[(size_t)a_m * K + kk] : 0.f;
        }
        __syncthreads();
        #pragma unroll
        for (int kk = 0; kk < 32; kk++) {
            float w = W[(size_t)(kb + kk) * N + n0 + col];
            #pragma unroll
            for (int r = 0; r < 8; r++) acc[r] += As[rq * 8 + r][kk] * w;
        }
        __syncthreads();
    }
    #pragma unroll
    for (int r = 0; r < 8; r++) {
        int m = rq * 8 + r;
        partial[((size_t)blockIdx.y * 32 + m) * N + n0 + col] = acc[r];
    }
}

__global__ void fc_reduce_relu(const float* __restrict__ partial,
                               const float* __restrict__ bias,
                               float* __restrict__ out, int N, int KS)
{
    int idx = blockIdx.x * blockDim.x + threadIdx.x;
    if (idx >= 32 * N) return;
    int m = idx / N, n = idx - m * N;
    float s = bias[n];
    for (int ks = 0; ks < KS; ks++)
        s += partial[((size_t)ks * 32 + m) * N + n];
    out[idx] = fmaxf(s, 0.f);
}

__global__ void fc3_softmax(const float* __restrict__ A, const float* __restrict__ W,
                            const float* __restrict__ bias, float* __restrict__ out)
{
    __shared__ float logits[32][5];
    int tid = threadIdx.x;
    int bm = tid >> 3, j = tid & 7;
    if (bm < 32 && j < 5) {
        float s = bias[j];
        for (int k = 0; k < 512; k++)
            s += A[bm * 512 + k] * W[k * 5 + j];
        logits[bm][j] = s;
    }
    __syncthreads();
    if (bm < 32 && j == 0) {
        float mx = logits[bm][0];
        for (int q = 1; q < 5; q++) mx = fmaxf(mx, logits[bm][q]);
        float e[5], sum = 0.f;
        for (int q = 0; q < 5; q++) { e[q] = expf(logits[bm][q] - mx); sum += e[q]; }
        for (int q = 0; q < 5; q++) out[bm * 5 + q] = e[q] / sum;
    }
}

// ================= host orchestration =================
extern "C" void kernel_launch(void* const* d_in, const int* in_sizes, int n_in,
                              void* d_out, int out_size)
{
    const float* x   = (const float*)d_in[0];
    const float* Wx1 = (const float*)d_in[1];
    const float* Wh1 = (const float*)d_in[2];
    const float* b1  = (const float*)d_in[3];
    const float* Wx2 = (const float*)d_in[4];
    const float* Wh2 = (const float*)d_in[5];
    const float* b2  = (const float*)d_in[6];
    const float* Wx3 = (const float*)d_in[7];
    const float* Wh3 = (const float*)d_in[8];
    const float* b3  = (const float*)d_in[9];
    const float* g1  = (const float*)d_in[10];
    const float* be1 = (const float*)d_in[11];
    const float* m1  = (const float*)d_in[12];
    const float* v1  = (const float*)d_in[13];
    const float* g2  = (const float*)d_in[14];
    const float* be2 = (const float*)d_in[15];
    const float* m2  = (const float*)d_in[16];
    const float* v2  = (const float*)d_in[17];
    const float* g3  = (const float*)d_in[18];
    const float* be3 = (const float*)d_in[19];
    const float* m3  = (const float*)d_in[20];
    const float* v3  = (const float*)d_in[21];
    const float* D1  = (const float*)d_in[22];
    const float* db1 = (const float*)d_in[23];
    const float* D2  = (const float*)d_in[24];
    const float* db2 = (const float*)d_in[25];
    const float* D3  = (const float*)d_in[26];
    const float* db3 = (const float*)d_in[27];
    float* out = (float*)d_out;

    float *xg1, *xg2, *xg3, *hst, *cst, *prt, *a1, *a2;
    float *pb1, *pb2, *pb3, *wx1p, *sc1, *sh1, *sc2, *sh2;
    __half *hf, *bn1f, *bn2f;
    __half *wh1, *wx2, *wh2, *wx3, *wh3;
    cudaGetSymbolAddress((void**)&xg1, g_xg1);
    cudaGetSymbolAddress((void**)&xg2, g_xg2);
    cudaGetSymbolAddress((void**)&xg3, g_xg3);
    cudaGetSymbolAddress((void**)&hst, g_hst);
    cudaGetSymbolAddress((void**)&cst, g_cst);
    cudaGetSymbolAddress((void**)&prt, g_prt);
    cudaGetSymbolAddress((void**)&a1,  g_a1);
    cudaGetSymbolAddress((void**)&a2,  g_a2);
    cudaGetSymbolAddress((void**)&pb1, g_pb1);
    cudaGetSymbolAddress((void**)&pb2, g_pb2);
    cudaGetSymbolAddress((void**)&pb3, g_pb3);
    cudaGetSymbolAddress((void**)&wx1p, g_wx1p);
    cudaGetSymbolAddress((void**)&sc1, g_sc1); cudaGetSymbolAddress((void**)&sh1, g_sh1);
    cudaGetSymbolAddress((void**)&sc2, g_sc2); cudaGetSymbolAddress((void**)&sh2, g_sh2);
    cudaGetSymbolAddress((void**)&hf,   g_hf);
    cudaGetSymbolAddress((void**)&bn1f, g_bn1f);
    cudaGetSymbolAddress((void**)&bn2f, g_bn2f);
    cudaGetSymbolAddress((void**)&wh1, g_wh1);
    cudaGetSymbolAddress((void**)&wx2, g_wx2);
    cudaGetSymbolAddress((void**)&wh2, g_wh2);
    cudaGetSymbolAddress((void**)&wx3, g_wx3);
    cudaGetSymbolAddress((void**)&wh3, g_wh3);

    const int Mall = BDIM * TDIM * LDIM;   // 131072
    const int Mst  = BDIM * LDIM;          // 4096
    const size_t HBUF = (size_t)BDIM * LDIM * 256;   // ping-pong stride (elems)
    const int SMEM_BIAS = 2 * BUFSZ;                 // 40960
    const int SMEM_GATE = 128 * STROW * 4;           // 67584 (> 2*BUFSZ)
    cudaFuncSetAttribute(mma_gemm_bias, cudaFuncAttributeMaxDynamicSharedMemorySize, SMEM_BIAS);
    cudaFuncSetAttribute(mma_gemm_gate, cudaFuncAttributeMaxDynamicSharedMemorySize, SMEM_GATE);
    dim3 blk(256);

    // ---- weight/bias conversions (gate-interleaved) ----
    wconv_kernel<<<(256*192  + 255)/256, 256>>>(Wh1, wh1, 192, 256);
    wconv_kernel<<<(512*192  + 255)/256, 256>>>(Wx2, wx2, 192, 512);
    wconv_kernel<<<(512*384  + 255)/256, 256>>>(Wh2, wh2, 384, 512);
    wconv_kernel<<<(1024*384 + 255)/256, 256>>>(Wx3, wx3, 384, 1024);
    wconv_kernel<<<(1024*768 + 255)/256, 256>>>(Wh3, wh3, 768, 1024);
    permute_bias<<<1, 256>>>(b1, pb1, 256);
    permute_bias<<<2, 256>>>(b2, pb2, 512);
    permute_bias<<<4, 256>>>(b3, pb3, 1024);
    permute_wx1<<<3, 256>>>(Wx1, wx1p);
    bn_prep<<<1, 64>>>(g1, be1, m1, v1, sc1, sh1, 64);
    bn_prep<<<1, 128>>>(g2, be2, m2, v2, sc2, sh2, 128);

    // ================= Layer 1 =================
    gemm_conv_kernel<<<dim3(2, Mall / BM), blk>>>(x, wx1p, pb1, xg1, Mall, 256, 3, 0);
    gate0_kernel<<<(Mst * 64 + 255) / 256, 256>>>(
        (const float4*)xg1, cst, hf, sc1, sh1, bn1f, Mst * 64, 6);
    for (int t = 1; t < TDIM; t++) {
        int pi = (t - 1) & 1, po = t & 1;
        mma_gemm_gate<<<dim3(2, Mst / 128), blk, SMEM_GATE>>>(
            hf + pi * HBUF, wh1,
            xg1 + (size_t)t * Mst * 256, cst, hf + po * HBUF,
            sc1, sh1, bn1f + (size_t)t * Mst * 64, nullptr,
            Mst, 256, 192, 6);
    }

    // ================= Layer 2 =================
    mma_gemm_bias<<<dim3(4, Mall / 128), blk, SMEM_BIAS>>>(
        bn1f, wx2, pb2, xg2, Mall, 512, 192, 6);
    gate0_kernel<<<(Mst * 128 + 255) / 256, 256>>>(
        (const float4*)xg2, cst, hf, sc2, sh2, bn2f, Mst * 128, 7);
    for (int t = 1; t < TDIM; t++) {
        int pi = (t - 1) & 1, po = t & 1;
        mma_gemm_gate<<<dim3(4, Mst / 128), blk, SMEM_GATE>>>(
            hf + pi * HBUF, wh2,
            xg2 + (size_t)t * Mst * 512, cst, hf + po * HBUF,
            sc2, sh2, bn2f + (size_t)t * Mst * 128, nullptr,
            Mst, 512, 384, 7);
    }

    // ================= Layer 3 =================
    mma_gemm_bias<<<dim3(8, Mall / 128), blk, SMEM_BIAS>>>(
        bn2f, wx3, pb3, xg3, Mall, 1024, 384, 7);
    gate0_kernel<<<(Mst * 256 + 255) / 256, 256>>>(
        (const float4*)xg3, cst, hf, nullptr, nullptr, nullptr, Mst * 256, 8);
    for (int t = 1; t < TDIM; t++) {
        int pi = (t - 1) & 1, po = t & 1;
        mma_gemm_gate<<<dim3(8, Mst / 128), blk, SMEM_GATE>>>(
            hf + pi * HBUF, wh3,
            xg3 + (size_t)t * Mst * 1024, cst, hf + po * HBUF,
            nullptr, nullptr, nullptr,
            (t == TDIM - 1) ? hst : nullptr,
            Mst, 1024, 768, 8);
    }
    {
        size_t tot = (size_t)Mst * 256;
        bn_kernel<<<(int)((tot + 255) / 256), 256>>>(hst, g3, be3, m3, v3, tot, 8);
    }

    // ================= Dense head =================
    fc_kernel<<<dim3(1024 / 64, 8), blk>>>(hst, D1, prt, 1024, 32768, 4096);
    fc_reduce_relu<<<(32 * 1024 + 255) / 256, 256>>>(prt, db1, a1, 1024, 8);
    fc_kernel<<<dim3(512 / 64, 2), blk>>>(a1, D2, prt, 512, 1024, 512);
    fc_reduce_relu<<<(32 * 512 + 255) / 256, 256>>>(prt, db2, a2, 512, 2);
    fc3_softmax<<<1, 256>>>(a2, D3, db3, out);
}